// round 2
// baseline (speedup 1.0000x reference)
#include <cuda_runtime.h>
#include <math.h>

#define NN 30000
#define EE 480000

// dims per layer: input 128 -> 16 -> 32 -> 64 -> 128 -> 256 -> 512
static const int DIMS[7] = {128, 16, 32, 64, 128, 256, 512};

// Scratch (static __device__ arrays; no allocations allowed)
__device__ float g_bufA[(size_t)NN * 512];
__device__ float g_bufB[(size_t)NN * 512];
__device__ float g_t1[(size_t)NN * 256];
__device__ float g_t2[(size_t)NN * 256];
__device__ float g_deg[NN];
__device__ float g_woff[EE];

// ---------------------------------------------------------------------------
// degree: deg[row[e]] += ew[e]
__global__ void deg_kernel(const int* __restrict__ row, const float* __restrict__ ew) {
    int e = blockIdx.x * blockDim.x + threadIdx.x;
    if (e < EE) atomicAdd(&g_deg[row[e]], ew[e]);
}

// w_off[e] = -(2/lmax) * ew[e] / deg[row[e]]  (lmax = 2 -> factor 1)
__global__ void woff_kernel(const int* __restrict__ row, const float* __restrict__ ew) {
    int e = blockIdx.x * blockDim.x + threadIdx.x;
    if (e < EE) {
        float d = g_deg[row[e]];
        g_woff[e] = (d > 0.f) ? (-ew[e] / d) : 0.f;
    }
}

// dst = -src (vectorized), used to init Tx2 = -Tx0 before scatter of 2*L*Tx1
__global__ void negcopy_kernel(const float4* __restrict__ src, float4* __restrict__ dst, int n4) {
    int i = blockIdx.x * blockDim.x + threadIdx.x;
    if (i < n4) {
        float4 v = src[i];
        dst[i] = make_float4(-v.x, -v.y, -v.z, -v.w);
    }
}

// dst[col[e]][:] += scale * w_off[e] * src[row[e]][:]
// one thread per (edge, 4 features)
__global__ void spmm_scatter(const float* __restrict__ src, float* __restrict__ dst,
                             const int* __restrict__ row, const int* __restrict__ col,
                             float scale, int F, int vecs) {
    int t = blockIdx.x * blockDim.x + threadIdx.x;
    int e = t / vecs;
    if (e >= EE) return;
    int f = (t - e * vecs) * 4;
    float w = g_woff[e] * scale;
    int r = row[e], c = col[e];
    const float4 v = *(const float4*)(src + (size_t)r * F + f);
    float* d = dst + (size_t)c * F + f;
    atomicAdd(d + 0, w * v.x);
    atomicAdd(d + 1, w * v.y);
    atomicAdd(d + 2, w * v.z);
    atomicAdd(d + 3, w * v.w);
}

__device__ __forceinline__ float softplusf(float x) {
    // logaddexp(x, 0) = max(x,0) + log1p(exp(-|x|)) — numerically stable
    return fmaxf(x, 0.f) + log1pf(__expf(-fabsf(x)));
}

// out = softplus( A0@W[0] + A1@W[1] + A2@W[2] + bias )
// W is (3, Fin, Fout). Tiled 64x64x8, 256 threads, 4x4 per thread.
__global__ void gemm3_kernel(const float* __restrict__ A0, const float* __restrict__ A1,
                             const float* __restrict__ A2, const float* __restrict__ W,
                             const float* __restrict__ bias, float* __restrict__ out,
                             int Fin, int Fout) {
    constexpr int BM = 64, BN = 64, BK = 8;
    __shared__ float sA[BK][BM];
    __shared__ float sB[BK][BN];
    const int bm = blockIdx.x * BM, bn = blockIdx.y * BN;
    const int tid = threadIdx.x;
    const int tx = tid & 15, ty = tid >> 4;

    float acc[4][4];
#pragma unroll
    for (int i = 0; i < 4; i++)
#pragma unroll
        for (int j = 0; j < 4; j++) acc[i][j] = 0.f;

    const float* As[3] = {A0, A1, A2};
    for (int k = 0; k < 3; k++) {
        const float* A = As[k];
        const float* Wk = W + (size_t)k * Fin * Fout;
        for (int i0 = 0; i0 < Fin; i0 += BK) {
#pragma unroll
            for (int l = 0; l < 2; l++) {
                int idx = tid + l * 256;         // 0..511 over BM*BK
                int mm = idx >> 3, kk = idx & 7;
                int m = bm + mm;
                sA[kk][mm] = (m < NN) ? A[(size_t)m * Fin + i0 + kk] : 0.f;
            }
#pragma unroll
            for (int l = 0; l < 2; l++) {
                int idx = tid + l * 256;         // 0..511 over BK*BN
                int kk = idx >> 6, nn = idx & 63;
                int n = bn + nn;
                sB[kk][nn] = (n < Fout) ? Wk[(size_t)(i0 + kk) * Fout + n] : 0.f;
            }
            __syncthreads();
#pragma unroll
            for (int kk = 0; kk < BK; kk++) {
                float a[4], b[4];
#pragma unroll
                for (int i = 0; i < 4; i++) a[i] = sA[kk][ty * 4 + i];
#pragma unroll
                for (int j = 0; j < 4; j++) b[j] = sB[kk][tx * 4 + j];
#pragma unroll
                for (int i = 0; i < 4; i++)
#pragma unroll
                    for (int j = 0; j < 4; j++) acc[i][j] = fmaf(a[i], b[j], acc[i][j]);
            }
            __syncthreads();
        }
    }

#pragma unroll
    for (int i = 0; i < 4; i++) {
        int m = bm + ty * 4 + i;
        if (m >= NN) continue;
#pragma unroll
        for (int j = 0; j < 4; j++) {
            int n = bn + tx * 4 + j;
            if (n < Fout) out[(size_t)m * Fout + n] = softplusf(acc[i][j] + bias[n]);
        }
    }
}

// final FC: out[n][0:3] = h[n][0:512] @ fc_w (512x3) + fc_b; one warp per node
__global__ void fc_kernel(const float* __restrict__ h, const float* __restrict__ fw,
                          const float* __restrict__ fb, float* __restrict__ out) {
    int gw = (blockIdx.x * blockDim.x + threadIdx.x) >> 5;
    int lane = threadIdx.x & 31;
    if (gw >= NN) return;
    const float* hr = h + (size_t)gw * 512;
    float a0 = 0.f, a1 = 0.f, a2 = 0.f;
    for (int i = lane; i < 512; i += 32) {
        float v = hr[i];
        a0 = fmaf(v, fw[i * 3 + 0], a0);
        a1 = fmaf(v, fw[i * 3 + 1], a1);
        a2 = fmaf(v, fw[i * 3 + 2], a2);
    }
#pragma unroll
    for (int o = 16; o > 0; o >>= 1) {
        a0 += __shfl_down_sync(0xffffffffu, a0, o);
        a1 += __shfl_down_sync(0xffffffffu, a1, o);
        a2 += __shfl_down_sync(0xffffffffu, a2, o);
    }
    if (lane == 0) {
        out[gw * 3 + 0] = a0 + fb[0];
        out[gw * 3 + 1] = a1 + fb[1];
        out[gw * 3 + 2] = a2 + fb[2];
    }
}

// ---------------------------------------------------------------------------

extern "C" void kernel_launch(void* const* d_in, const int* in_sizes, int n_in,
                              void* d_out, int out_size) {
    (void)in_sizes; (void)n_in; (void)out_size;

    const float* x   = (const float*)d_in[0];
    const int*   ei  = (const int*)d_in[1];   // (2, E): row = ei[0..E), col = ei[E..2E)
    const float* ew  = (const float*)d_in[2];
    // d_in[3] = batch (identity pooling, unused)
    const float* Wp[6];
    const float* bp[6];
    for (int l = 0; l < 6; l++) {
        Wp[l] = (const float*)d_in[4 + 2 * l];
        bp[l] = (const float*)d_in[5 + 2 * l];
    }
    const float* fcw = (const float*)d_in[16];
    const float* fcb = (const float*)d_in[17];
    float* out = (float*)d_out;

    float *bufA, *bufB, *t1, *t2, *deg;
    cudaGetSymbolAddress((void**)&bufA, g_bufA);
    cudaGetSymbolAddress((void**)&bufB, g_bufB);
    cudaGetSymbolAddress((void**)&t1,   g_t1);
    cudaGetSymbolAddress((void**)&t2,   g_t2);
    cudaGetSymbolAddress((void**)&deg,  g_deg);

    const int* row = ei;
    const int* col = ei + EE;

    // degree + normalized off-diagonal weights (computed fresh every call)
    cudaMemsetAsync(deg, 0, NN * sizeof(float));
    deg_kernel<<<(EE + 255) / 256, 256>>>(row, ew);
    woff_kernel<<<(EE + 255) / 256, 256>>>(row, ew);

    const float* h = x;      // layer input
    float* pOut = bufA;      // layer output (ping-pong)
    float* pAlt = bufB;

    for (int l = 0; l < 6; l++) {
        int Fin = DIMS[l], Fout = DIMS[l + 1];
        int vecs = Fin / 4;
        long tthreads = (long)EE * vecs;
        unsigned sblocks = (unsigned)((tthreads + 255) / 256);

        // Tx1 = L h
        cudaMemsetAsync(t1, 0, (size_t)NN * Fin * sizeof(float));
        spmm_scatter<<<sblocks, 256>>>(h, t1, row, col, 1.f, Fin, vecs);

        // Tx2 = 2 L Tx1 - h : init to -h, scatter with scale 2
        int n4 = NN * Fin / 4;
        negcopy_kernel<<<(n4 + 255) / 256, 256>>>((const float4*)h, (float4*)t2, n4);
        spmm_scatter<<<sblocks, 256>>>(t1, t2, row, col, 2.f, Fin, vecs);

        // out = softplus(h@W0 + Tx1@W1 + Tx2@W2 + b)
        dim3 grid((NN + 63) / 64, (Fout + 63) / 64);
        gemm3_kernel<<<grid, 256>>>(h, t1, t2, Wp[l], bp[l], pOut, Fin, Fout);

        h = pOut;
        float* tmp = pOut; pOut = pAlt; pAlt = tmp;
    }

    // final FC 512 -> 3
    fc_kernel<<<((long)NN * 32 + 255) / 256, 256>>>(h, fcw, fcb, out);
}

// round 3
// speedup vs baseline: 1.7816x; 1.7816x over previous
#include <cuda_runtime.h>
#include <math.h>

#define NN 30000
#define EE 480000

// dims per layer: input 128 -> 16 -> 32 -> 64 -> 128 -> 256 -> 512
static const int DIMS[7] = {128, 16, 32, 64, 128, 256, 512};

// Scratch (static __device__ arrays; no allocations allowed)
__device__ float g_bufA[(size_t)NN * 512];
__device__ float g_bufB[(size_t)NN * 512];
__device__ float g_t1[(size_t)NN * 256];
__device__ float g_t2[(size_t)NN * 256];
__device__ float g_deg[NN];
__device__ int   g_cnt[NN];
__device__ int   g_ptr[NN + 1];
__device__ int   g_cur[NN];
__device__ int   g_srcidx[EE];   // row indices sorted by destination column
__device__ float g_wsort[EE];    // normalized edge weights sorted by destination column

// ---------------------------------------------------------------------------
// Pass 1: deg[row[e]] += ew[e];  cnt[col[e]] += 1
__global__ void deg_count_kernel(const int* __restrict__ row, const int* __restrict__ col,
                                 const float* __restrict__ ew) {
    int e = blockIdx.x * blockDim.x + threadIdx.x;
    if (e < EE) {
        atomicAdd(&g_deg[row[e]], ew[e]);
        atomicAdd(&g_cnt[col[e]], 1);
    }
}

// Pass 2: exclusive prefix sum of cnt -> ptr, cur (single block, chunked Hillis-Steele)
__global__ void scan_kernel() {
    constexpr int B = 1024;
    __shared__ int sdata[B];
    __shared__ int s_off;
    if (threadIdx.x == 0) s_off = 0;
    __syncthreads();
    for (int base = 0; base < NN; base += B) {
        int i = base + threadIdx.x;
        int v = (i < NN) ? g_cnt[i] : 0;
        sdata[threadIdx.x] = v;
        __syncthreads();
        for (int o = 1; o < B; o <<= 1) {
            int t = (threadIdx.x >= o) ? sdata[threadIdx.x - o] : 0;
            __syncthreads();
            sdata[threadIdx.x] += t;
            __syncthreads();
        }
        int excl = sdata[threadIdx.x] - v;
        if (i < NN) {
            g_ptr[i] = s_off + excl;
            g_cur[i] = s_off + excl;
        }
        int total = sdata[B - 1];
        __syncthreads();
        if (threadIdx.x == 0) s_off += total;
        __syncthreads();
    }
    if (threadIdx.x == 0) g_ptr[NN] = s_off;
}

// Pass 3: scatter edges into CSC slots; compute normalized weight on the way
__global__ void fill_kernel(const int* __restrict__ row, const int* __restrict__ col,
                            const float* __restrict__ ew) {
    int e = blockIdx.x * blockDim.x + threadIdx.x;
    if (e < EE) {
        int c = col[e];
        int p = atomicAdd(&g_cur[c], 1);
        int r = row[e];
        g_srcidx[p] = r;
        float d = g_deg[r];
        g_wsort[p] = (d > 0.f) ? (-ew[e] / d) : 0.f;   // -(2/lmax) * ew / deg, lmax=2
    }
}

// ---------------------------------------------------------------------------
// Gather SpMM: dst[c] = scale * sum_{e in col c} w[e]*src[srcidx[e]]  (+ addscale*addsrc[c])
// threads: x = FV float4-lanes of the feature dim, y = nodes per block
__global__ void spmm_gather(const float4* __restrict__ src, const float4* __restrict__ addsrc,
                            float scale, float addscale, float4* __restrict__ dst,
                            int FV, int npb) {
    int ty = threadIdx.x / FV;
    int tx = threadIdx.x - ty * FV;
    int c = blockIdx.x * npb + ty;
    if (c >= NN) return;
    int beg = g_ptr[c], end = g_ptr[c + 1];
    float4 acc = make_float4(0.f, 0.f, 0.f, 0.f);
    for (int e = beg; e < end; e++) {
        int r = g_srcidx[e];          // broadcast across x-lanes
        float w = g_wsort[e];
        float4 v = src[(size_t)r * FV + tx];
        acc.x = fmaf(w, v.x, acc.x);
        acc.y = fmaf(w, v.y, acc.y);
        acc.z = fmaf(w, v.z, acc.z);
        acc.w = fmaf(w, v.w, acc.w);
    }
    float4 o = make_float4(scale * acc.x, scale * acc.y, scale * acc.z, scale * acc.w);
    if (addsrc) {
        float4 a = addsrc[(size_t)c * FV + tx];
        o.x = fmaf(addscale, a.x, o.x);
        o.y = fmaf(addscale, a.y, o.y);
        o.z = fmaf(addscale, a.z, o.z);
        o.w = fmaf(addscale, a.w, o.w);
    }
    dst[(size_t)c * FV + tx] = o;
}

__device__ __forceinline__ float softplusf(float x) {
    return fmaxf(x, 0.f) + log1pf(__expf(-fabsf(x)));
}

// ---------------------------------------------------------------------------
// Big GEMM: out = softplus([A0|A1|A2] @ [W0;W1;W2] + bias), 128x128x8 tiles,
// 256 threads, 8x8 per thread. Requires Fout % 128 == 0, Fin % 8 == 0.
__global__ void gemm3_big(const float* __restrict__ A0, const float* __restrict__ A1,
                          const float* __restrict__ A2, const float* __restrict__ W,
                          const float* __restrict__ bias, float* __restrict__ out,
                          int Fin, int Fout) {
    constexpr int BM = 128, BN = 128, BK = 8;
    __shared__ float sA[BK][BM];
    __shared__ float sB[BK][BN];
    const int bm = blockIdx.x * BM, bn = blockIdx.y * BN;
    const int tid = threadIdx.x;
    const int tx = tid & 15, ty = tid >> 4;     // 16x16 threads, 8x8 each

    float acc[8][8];
#pragma unroll
    for (int i = 0; i < 8; i++)
#pragma unroll
        for (int j = 0; j < 8; j++) acc[i][j] = 0.f;

    const float* As[3] = {A0, A1, A2};
    const int KT = 3 * Fin;

    // A-load mapping: thread loads one float4: row = tid>>1, k-offset = (tid&1)*4
    const int la_r = tid >> 1, la_k = (tid & 1) * 4;
    // B-load mapping: kk = tid>>5, col-offset = (tid&31)*4
    const int lb_k = tid >> 5, lb_n = (tid & 31) * 4;

    for (int i0 = 0; i0 < KT; i0 += BK) {
        int seg = i0 / Fin;
        int koff = i0 - seg * Fin;
        const float* A = As[seg];

        int m = bm + la_r;
        float4 av = make_float4(0.f, 0.f, 0.f, 0.f);
        if (m < NN) av = *(const float4*)(A + (size_t)m * Fin + koff + la_k);
        sA[la_k + 0][la_r] = av.x;
        sA[la_k + 1][la_r] = av.y;
        sA[la_k + 2][la_r] = av.z;
        sA[la_k + 3][la_r] = av.w;

        float4 bv = *(const float4*)(W + (size_t)(i0 + lb_k) * Fout + bn + lb_n);
        *(float4*)&sB[lb_k][lb_n] = bv;

        __syncthreads();
#pragma unroll
        for (int kk = 0; kk < BK; kk++) {
            float4 a01 = *(const float4*)&sA[kk][ty * 8];
            float4 a23 = *(const float4*)&sA[kk][ty * 8 + 4];
            float4 b01 = *(const float4*)&sB[kk][tx * 8];
            float4 b23 = *(const float4*)&sB[kk][tx * 8 + 4];
            float a[8] = {a01.x, a01.y, a01.z, a01.w, a23.x, a23.y, a23.z, a23.w};
            float b[8] = {b01.x, b01.y, b01.z, b01.w, b23.x, b23.y, b23.z, b23.w};
#pragma unroll
            for (int i = 0; i < 8; i++)
#pragma unroll
                for (int j = 0; j < 8; j++) acc[i][j] = fmaf(a[i], b[j], acc[i][j]);
        }
        __syncthreads();
    }

#pragma unroll
    for (int i = 0; i < 8; i++) {
        int m = bm + ty * 8 + i;
        if (m >= NN) continue;
#pragma unroll
        for (int j = 0; j < 8; j++) {
            int n = bn + tx * 8 + j;
            out[(size_t)m * Fout + n] = softplusf(acc[i][j] + bias[n]);
        }
    }
}

// Small GEMM (Fout <= 64): 64x64x8 tiles, 256 threads, 4x4 per thread.
__global__ void gemm3_small(const float* __restrict__ A0, const float* __restrict__ A1,
                            const float* __restrict__ A2, const float* __restrict__ W,
                            const float* __restrict__ bias, float* __restrict__ out,
                            int Fin, int Fout) {
    constexpr int BM = 64, BN = 64, BK = 8;
    __shared__ float sA[BK][BM];
    __shared__ float sB[BK][BN];
    const int bm = blockIdx.x * BM, bn = blockIdx.y * BN;
    const int tid = threadIdx.x;
    const int tx = tid & 15, ty = tid >> 4;

    float acc[4][4];
#pragma unroll
    for (int i = 0; i < 4; i++)
#pragma unroll
        for (int j = 0; j < 4; j++) acc[i][j] = 0.f;

    const float* As[3] = {A0, A1, A2};
    for (int k = 0; k < 3; k++) {
        const float* A = As[k];
        const float* Wk = W + (size_t)k * Fin * Fout;
        for (int i0 = 0; i0 < Fin; i0 += BK) {
#pragma unroll
            for (int l = 0; l < 2; l++) {
                int idx = tid + l * 256;
                int mm = idx >> 3, kk = idx & 7;
                int m = bm + mm;
                sA[kk][mm] = (m < NN) ? A[(size_t)m * Fin + i0 + kk] : 0.f;
            }
#pragma unroll
            for (int l = 0; l < 2; l++) {
                int idx = tid + l * 256;
                int kk = idx >> 6, nn = idx & 63;
                int n = bn + nn;
                sB[kk][nn] = (n < Fout) ? Wk[(size_t)(i0 + kk) * Fout + n] : 0.f;
            }
            __syncthreads();
#pragma unroll
            for (int kk = 0; kk < BK; kk++) {
                float a[4], b[4];
#pragma unroll
                for (int i = 0; i < 4; i++) a[i] = sA[kk][ty * 4 + i];
#pragma unroll
                for (int j = 0; j < 4; j++) b[j] = sB[kk][tx * 4 + j];
#pragma unroll
                for (int i = 0; i < 4; i++)
#pragma unroll
                    for (int j = 0; j < 4; j++) acc[i][j] = fmaf(a[i], b[j], acc[i][j]);
            }
            __syncthreads();
        }
    }

#pragma unroll
    for (int i = 0; i < 4; i++) {
        int m = bm + ty * 4 + i;
        if (m >= NN) continue;
#pragma unroll
        for (int j = 0; j < 4; j++) {
            int n = bn + tx * 4 + j;
            if (n < Fout) out[(size_t)m * Fout + n] = softplusf(acc[i][j] + bias[n]);
        }
    }
}

// final FC: out[n][0:3] = h[n][0:512] @ fc_w (512x3) + fc_b; one warp per node
__global__ void fc_kernel(const float* __restrict__ h, const float* __restrict__ fw,
                          const float* __restrict__ fb, float* __restrict__ out) {
    int gw = (blockIdx.x * blockDim.x + threadIdx.x) >> 5;
    int lane = threadIdx.x & 31;
    if (gw >= NN) return;
    const float* hr = h + (size_t)gw * 512;
    float a0 = 0.f, a1 = 0.f, a2 = 0.f;
    for (int i = lane; i < 512; i += 32) {
        float v = hr[i];
        a0 = fmaf(v, fw[i * 3 + 0], a0);
        a1 = fmaf(v, fw[i * 3 + 1], a1);
        a2 = fmaf(v, fw[i * 3 + 2], a2);
    }
#pragma unroll
    for (int o = 16; o > 0; o >>= 1) {
        a0 += __shfl_down_sync(0xffffffffu, a0, o);
        a1 += __shfl_down_sync(0xffffffffu, a1, o);
        a2 += __shfl_down_sync(0xffffffffu, a2, o);
    }
    if (lane == 0) {
        out[gw * 3 + 0] = a0 + fb[0];
        out[gw * 3 + 1] = a1 + fb[1];
        out[gw * 3 + 2] = a2 + fb[2];
    }
}

// ---------------------------------------------------------------------------

extern "C" void kernel_launch(void* const* d_in, const int* in_sizes, int n_in,
                              void* d_out, int out_size) {
    (void)in_sizes; (void)n_in; (void)out_size;

    const float* x   = (const float*)d_in[0];
    const int*   ei  = (const int*)d_in[1];   // (2, E)
    const float* ew  = (const float*)d_in[2];
    const float* Wp[6];
    const float* bp[6];
    for (int l = 0; l < 6; l++) {
        Wp[l] = (const float*)d_in[4 + 2 * l];
        bp[l] = (const float*)d_in[5 + 2 * l];
    }
    const float* fcw = (const float*)d_in[16];
    const float* fcb = (const float*)d_in[17];
    float* out = (float*)d_out;

    float *bufA, *bufB, *t1, *t2, *deg;
    int *cnt;
    cudaGetSymbolAddress((void**)&bufA, g_bufA);
    cudaGetSymbolAddress((void**)&bufB, g_bufB);
    cudaGetSymbolAddress((void**)&t1,   g_t1);
    cudaGetSymbolAddress((void**)&t2,   g_t2);
    cudaGetSymbolAddress((void**)&deg,  g_deg);
    cudaGetSymbolAddress((void**)&cnt,  g_cnt);

    const int* row = ei;
    const int* col = ei + EE;

    // CSC build (fresh each call)
    cudaMemsetAsync(deg, 0, NN * sizeof(float));
    cudaMemsetAsync(cnt, 0, NN * sizeof(int));
    deg_count_kernel<<<(EE + 255) / 256, 256>>>(row, col, ew);
    scan_kernel<<<1, 1024>>>();
    fill_kernel<<<(EE + 255) / 256, 256>>>(row, col, ew);

    const float* h = x;      // layer input
    float* pOut = bufA;      // layer output (ping-pong)
    float* pAlt = bufB;

    for (int l = 0; l < 6; l++) {
        int Fin = DIMS[l], Fout = DIMS[l + 1];
        int FV = Fin / 4;
        int npb = 256 / FV;
        unsigned gblocks = (unsigned)((NN + npb - 1) / npb);

        // Tx1 = L h
        spmm_gather<<<gblocks, 256>>>((const float4*)h, nullptr, 1.f, 0.f,
                                      (float4*)t1, FV, npb);
        // Tx2 = 2 L Tx1 - h
        spmm_gather<<<gblocks, 256>>>((const float4*)t1, (const float4*)h, 2.f, -1.f,
                                      (float4*)t2, FV, npb);

        // out = softplus(h@W0 + Tx1@W1 + Tx2@W2 + b)
        if (Fout >= 128) {
            dim3 grid((NN + 127) / 128, Fout / 128);
            gemm3_big<<<grid, 256>>>(h, t1, t2, Wp[l], bp[l], pOut, Fin, Fout);
        } else {
            dim3 grid((NN + 63) / 64, (Fout + 63) / 64);
            gemm3_small<<<grid, 256>>>(h, t1, t2, Wp[l], bp[l], pOut, Fin, Fout);
        }

        h = pOut;
        float* tmp = pOut; pOut = pAlt; pAlt = tmp;
    }

    // final FC 512 -> 3
    fc_kernel<<<((long)NN * 32 + 255) / 256, 256>>>(h, fcw, fcb, out);
}

// round 6
// speedup vs baseline: 3.0668x; 1.7214x over previous
#include <cuda_runtime.h>
#include <math.h>
#include <stdint.h>

#define NN 30000
#define EE 480000

// dims per layer: input 128 -> 16 -> 32 -> 64 -> 128 -> 256 -> 512
static const int DIMS[7] = {128, 16, 32, 64, 128, 256, 512};

// Scratch (static __device__ arrays; no allocations allowed)
__device__ float g_bufA[(size_t)NN * 512];
__device__ float g_bufB[(size_t)NN * 512];
__device__ float g_t1[(size_t)NN * 256];
__device__ float g_t2[(size_t)NN * 256];
__device__ float g_deg[NN];
__device__ int   g_cnt[NN];
__device__ int   g_ptr[NN + 1];
__device__ int   g_cur[NN];
__device__ int   g_srcidx[EE];   // row indices sorted by destination column
__device__ float g_wsort[EE];    // normalized edge weights sorted by destination column

// ---------------------------------------------------------------------------
// Pass 1: deg[row[e]] += ew[e];  cnt[col[e]] += 1
__global__ void deg_count_kernel(const int* __restrict__ row, const int* __restrict__ col,
                                 const float* __restrict__ ew) {
    int e = blockIdx.x * blockDim.x + threadIdx.x;
    if (e < EE) {
        atomicAdd(&g_deg[row[e]], ew[e]);
        atomicAdd(&g_cnt[col[e]], 1);
    }
}

// Pass 2: exclusive prefix sum of cnt -> ptr, cur (single block, chunked Hillis-Steele)
__global__ void scan_kernel() {
    constexpr int B = 1024;
    __shared__ int sdata[B];
    __shared__ int s_off;
    if (threadIdx.x == 0) s_off = 0;
    __syncthreads();
    for (int base = 0; base < NN; base += B) {
        int i = base + threadIdx.x;
        int v = (i < NN) ? g_cnt[i] : 0;
        sdata[threadIdx.x] = v;
        __syncthreads();
        for (int o = 1; o < B; o <<= 1) {
            int t = (threadIdx.x >= o) ? sdata[threadIdx.x - o] : 0;
            __syncthreads();
            sdata[threadIdx.x] += t;
            __syncthreads();
        }
        int excl = sdata[threadIdx.x] - v;
        if (i < NN) {
            g_ptr[i] = s_off + excl;
            g_cur[i] = s_off + excl;
        }
        int total = sdata[B - 1];
        __syncthreads();
        if (threadIdx.x == 0) s_off += total;
        __syncthreads();
    }
    if (threadIdx.x == 0) g_ptr[NN] = s_off;
}

// Pass 3: scatter edges into CSC slots; compute normalized weight on the way
__global__ void fill_kernel(const int* __restrict__ row, const int* __restrict__ col,
                            const float* __restrict__ ew) {
    int e = blockIdx.x * blockDim.x + threadIdx.x;
    if (e < EE) {
        int c = col[e];
        int p = atomicAdd(&g_cur[c], 1);
        int r = row[e];
        g_srcidx[p] = r;
        float d = g_deg[r];
        g_wsort[p] = (d > 0.f) ? (-ew[e] / d) : 0.f;   // -(2/lmax) * ew / deg, lmax=2
    }
}

// ---------------------------------------------------------------------------
// Gather SpMM: dst[c] = scale * sum_{e in col c} w[e]*src[srcidx[e]]  (+ addscale*addsrc[c])
__global__ void spmm_gather(const float4* __restrict__ src, const float4* __restrict__ addsrc,
                            float scale, float addscale, float4* __restrict__ dst,
                            int FV, int npb) {
    int ty = threadIdx.x / FV;
    int tx = threadIdx.x - ty * FV;
    int c = blockIdx.x * npb + ty;
    if (c >= NN) return;
    int beg = g_ptr[c], end = g_ptr[c + 1];
    float4 acc = make_float4(0.f, 0.f, 0.f, 0.f);
    for (int e = beg; e < end; e++) {
        int r = g_srcidx[e];
        float w = g_wsort[e];
        float4 v = src[(size_t)r * FV + tx];
        acc.x = fmaf(w, v.x, acc.x);
        acc.y = fmaf(w, v.y, acc.y);
        acc.z = fmaf(w, v.z, acc.z);
        acc.w = fmaf(w, v.w, acc.w);
    }
    float4 o = make_float4(scale * acc.x, scale * acc.y, scale * acc.z, scale * acc.w);
    if (addsrc) {
        float4 a = addsrc[(size_t)c * FV + tx];
        o.x = fmaf(addscale, a.x, o.x);
        o.y = fmaf(addscale, a.y, o.y);
        o.z = fmaf(addscale, a.z, o.z);
        o.w = fmaf(addscale, a.w, o.w);
    }
    dst[(size_t)c * FV + tx] = o;
}

__device__ __forceinline__ float softplusf(float x) {
    return fmaxf(x, 0.f) + log1pf(__expf(-fabsf(x)));
}

__device__ __forceinline__ uint32_t f2tf32(float f) {
    uint32_t u;
    asm("cvt.rna.tf32.f32 %0, %1;" : "=r"(u) : "f"(f));
    return u;
}

__device__ __forceinline__ void mma_tf32(float (&d)[4], const uint32_t (&a)[4],
                                         const uint32_t (&b)[2]) {
    asm volatile(
        "mma.sync.aligned.m16n8k8.row.col.f32.tf32.tf32.f32 "
        "{%0,%1,%2,%3},{%4,%5,%6,%7},{%8,%9},{%0,%1,%2,%3};"
        : "+f"(d[0]), "+f"(d[1]), "+f"(d[2]), "+f"(d[3])
        : "r"(a[0]), "r"(a[1]), "r"(a[2]), "r"(a[3]), "r"(b[0]), "r"(b[1]));
}

// ---------------------------------------------------------------------------
// Tensor-core GEMM (tf32): out = softplus([A0|A1|A2] @ [W0;W1;W2] + bias)
// 128x128x16 block tile, 8 warps, each warp 64x32 (4 m-frags x 4 n-frags).
// Requires Fout % 128 == 0, Fin % 16 == 0.
__global__ __launch_bounds__(256) void gemm3_tc(
        const float* __restrict__ A0, const float* __restrict__ A1,
        const float* __restrict__ A2, const float* __restrict__ W,
        const float* __restrict__ bias, float* __restrict__ out,
        int Fin, int Fout) {
    constexpr int BM = 128, BN = 128, BK = 16;
    constexpr int SAS = 136;  // [k][m] stride (mod 32 == 8 -> conflict-free frags)
    constexpr int SBS = 136;  // [k][n] stride
    __shared__ __align__(16) uint32_t sA[BK * SAS];
    __shared__ __align__(16) uint32_t sB[BK * SBS];

    const int tid = threadIdx.x;
    const int lane = tid & 31;
    const int warp = tid >> 5;
    const int warp_m = warp & 1;    // 0..1 -> 64 rows each
    const int warp_n = warp >> 1;   // 0..3 -> 32 cols each
    const int bm = blockIdx.x * BM, bn = blockIdx.y * BN;
    const int grp = lane >> 2;      // 0..7
    const int tig = lane & 3;       // 0..3

    float acc[4][4][4];
#pragma unroll
    for (int i = 0; i < 4; i++)
#pragma unroll
        for (int j = 0; j < 4; j++)
#pragma unroll
            for (int v = 0; v < 4; v++) acc[i][j][v] = 0.f;

    const float* As[3] = {A0, A1, A2};
    const int KT = 3 * Fin;

    for (int k0 = 0; k0 < KT; k0 += BK) {
        const int seg = k0 / Fin;
        const int koff = k0 - seg * Fin;
        const float* A = As[seg];

        // Load A tile -> sA[k][m] (transposed), converting to tf32.
        // Thread t loads float4 at (m = t/4 + it*64, k = (t&3)*4).
#pragma unroll
        for (int it = 0; it < 2; it++) {
            int m = (tid >> 2) + it * 64;
            int kk = (tid & 3) * 4;
            int gm = bm + m;
            float4 v = make_float4(0.f, 0.f, 0.f, 0.f);
            if (gm < NN) v = *(const float4*)(A + (size_t)gm * Fin + koff + kk);
            sA[(kk + 0) * SAS + m] = f2tf32(v.x);
            sA[(kk + 1) * SAS + m] = f2tf32(v.y);
            sA[(kk + 2) * SAS + m] = f2tf32(v.z);
            sA[(kk + 3) * SAS + m] = f2tf32(v.w);
        }
        // Load B tile -> sB[k][n]. W is (3*Fin, Fout) row-major; k0 indexes it directly.
#pragma unroll
        for (int it = 0; it < 2; it++) {
            int kk = (tid >> 5) + it * 8;
            int n = (tid & 31) * 4;
            float4 v = *(const float4*)(W + (size_t)(k0 + kk) * Fout + bn + n);
            uint4 u;
            u.x = f2tf32(v.x); u.y = f2tf32(v.y); u.z = f2tf32(v.z); u.w = f2tf32(v.w);
            *(uint4*)&sB[kk * SBS + n] = u;
        }
        __syncthreads();

#pragma unroll
        for (int ks = 0; ks < BK; ks += 8) {
            uint32_t af[4][4];
            uint32_t bf[4][2];
#pragma unroll
            for (int mf = 0; mf < 4; mf++) {
                int m = warp_m * 64 + mf * 16 + grp;
                af[mf][0] = sA[(ks + tig) * SAS + m];
                af[mf][1] = sA[(ks + tig) * SAS + m + 8];
                af[mf][2] = sA[(ks + tig + 4) * SAS + m];
                af[mf][3] = sA[(ks + tig + 4) * SAS + m + 8];
            }
#pragma unroll
            for (int nf = 0; nf < 4; nf++) {
                int n = warp_n * 32 + nf * 8 + grp;
                bf[nf][0] = sB[(ks + tig) * SBS + n];
                bf[nf][1] = sB[(ks + tig + 4) * SBS + n];
            }
#pragma unroll
            for (int mf = 0; mf < 4; mf++)
#pragma unroll
                for (int nf = 0; nf < 4; nf++)
                    mma_tf32(acc[mf][nf], af[mf], bf[nf]);
        }
        __syncthreads();
    }

    // Epilogue: c0 (row=grp, col=2*tig), c1 (+1), c2 (row=grp+8), c3 (+1)
#pragma unroll
    for (int mf = 0; mf < 4; mf++) {
        int m0 = bm + warp_m * 64 + mf * 16 + grp;
#pragma unroll
        for (int nf = 0; nf < 4; nf++) {
            int n0 = bn + warp_n * 32 + nf * 8 + 2 * tig;
            float b0 = bias[n0], b1 = bias[n0 + 1];
            if (m0 < NN) {
                float* d = out + (size_t)m0 * Fout + n0;
                d[0] = softplusf(acc[mf][nf][0] + b0);
                d[1] = softplusf(acc[mf][nf][1] + b1);
            }
            if (m0 + 8 < NN) {
                float* d = out + (size_t)(m0 + 8) * Fout + n0;
                d[0] = softplusf(acc[mf][nf][2] + b0);
                d[1] = softplusf(acc[mf][nf][3] + b1);
            }
        }
    }
}

// Small GEMM (Fout <= 64): 64x64x8 tiles, 256 threads, 4x4 per thread.
__global__ void gemm3_small(const float* __restrict__ A0, const float* __restrict__ A1,
                            const float* __restrict__ A2, const float* __restrict__ W,
                            const float* __restrict__ bias, float* __restrict__ out,
                            int Fin, int Fout) {
    constexpr int BM = 64, BN = 64, BK = 8;
    __shared__ float sA[BK][BM];
    __shared__ float sB[BK][BN];
    const int bm = blockIdx.x * BM, bn = blockIdx.y * BN;
    const int tid = threadIdx.x;
    const int tx = tid & 15, ty = tid >> 4;

    float acc[4][4];
#pragma unroll
    for (int i = 0; i < 4; i++)
#pragma unroll
        for (int j = 0; j < 4; j++) acc[i][j] = 0.f;

    const float* As[3] = {A0, A1, A2};
    for (int k = 0; k < 3; k++) {
        const float* A = As[k];
        const float* Wk = W + (size_t)k * Fin * Fout;
        for (int i0 = 0; i0 < Fin; i0 += BK) {
#pragma unroll
            for (int l = 0; l < 2; l++) {
                int idx = tid + l * 256;
                int mm = idx >> 3, kk = idx & 7;
                int m = bm + mm;
                sA[kk][mm] = (m < NN) ? A[(size_t)m * Fin + i0 + kk] : 0.f;
            }
#pragma unroll
            for (int l = 0; l < 2; l++) {
                int idx = tid + l * 256;
                int kk = idx >> 6, nn = idx & 63;
                int n = bn + nn;
                sB[kk][nn] = (n < Fout) ? Wk[(size_t)(i0 + kk) * Fout + n] : 0.f;
            }
            __syncthreads();
#pragma unroll
            for (int kk = 0; kk < BK; kk++) {
                float a[4], b[4];
#pragma unroll
                for (int i = 0; i < 4; i++) a[i] = sA[kk][ty * 4 + i];
#pragma unroll
                for (int j = 0; j < 4; j++) b[j] = sB[kk][tx * 4 + j];
#pragma unroll
                for (int i = 0; i < 4; i++)
#pragma unroll
                    for (int j = 0; j < 4; j++) acc[i][j] = fmaf(a[i], b[j], acc[i][j]);
            }
            __syncthreads();
        }
    }

#pragma unroll
    for (int i = 0; i < 4; i++) {
        int m = bm + ty * 4 + i;
        if (m >= NN) continue;
#pragma unroll
        for (int j = 0; j < 4; j++) {
            int n = bn + tx * 4 + j;
            if (n < Fout) out[(size_t)m * Fout + n] = softplusf(acc[i][j] + bias[n]);
        }
    }
}

// final FC: out[n][0:3] = h[n][0:512] @ fc_w (512x3) + fc_b; one warp per node
__global__ void fc_kernel(const float* __restrict__ h, const float* __restrict__ fw,
                          const float* __restrict__ fb, float* __restrict__ out) {
    int gw = (blockIdx.x * blockDim.x + threadIdx.x) >> 5;
    int lane = threadIdx.x & 31;
    if (gw >= NN) return;
    const float* hr = h + (size_t)gw * 512;
    float a0 = 0.f, a1 = 0.f, a2 = 0.f;
    for (int i = lane; i < 512; i += 32) {
        float v = hr[i];
        a0 = fmaf(v, fw[i * 3 + 0], a0);
        a1 = fmaf(v, fw[i * 3 + 1], a1);
        a2 = fmaf(v, fw[i * 3 + 2], a2);
    }
#pragma unroll
    for (int o = 16; o > 0; o >>= 1) {
        a0 += __shfl_down_sync(0xffffffffu, a0, o);
        a1 += __shfl_down_sync(0xffffffffu, a1, o);
        a2 += __shfl_down_sync(0xffffffffu, a2, o);
    }
    if (lane == 0) {
        out[gw * 3 + 0] = a0 + fb[0];
        out[gw * 3 + 1] = a1 + fb[1];
        out[gw * 3 + 2] = a2 + fb[2];
    }
}

// ---------------------------------------------------------------------------

extern "C" void kernel_launch(void* const* d_in, const int* in_sizes, int n_in,
                              void* d_out, int out_size) {
    (void)in_sizes; (void)n_in; (void)out_size;

    const float* x   = (const float*)d_in[0];
    const int*   ei  = (const int*)d_in[1];   // (2, E)
    const float* ew  = (const float*)d_in[2];
    const float* Wp[6];
    const float* bp[6];
    for (int l = 0; l < 6; l++) {
        Wp[l] = (const float*)d_in[4 + 2 * l];
        bp[l] = (const float*)d_in[5 + 2 * l];
    }
    const float* fcw = (const float*)d_in[16];
    const float* fcb = (const float*)d_in[17];
    float* out = (float*)d_out;

    float *bufA, *bufB, *t1, *t2, *deg;
    int *cnt;
    cudaGetSymbolAddress((void**)&bufA, g_bufA);
    cudaGetSymbolAddress((void**)&bufB, g_bufB);
    cudaGetSymbolAddress((void**)&t1,   g_t1);
    cudaGetSymbolAddress((void**)&t2,   g_t2);
    cudaGetSymbolAddress((void**)&deg,  g_deg);
    cudaGetSymbolAddress((void**)&cnt,  g_cnt);

    const int* row = ei;
    const int* col = ei + EE;

    // CSC build (fresh each call)
    cudaMemsetAsync(deg, 0, NN * sizeof(float));
    cudaMemsetAsync(cnt, 0, NN * sizeof(int));
    deg_count_kernel<<<(EE + 255) / 256, 256>>>(row, col, ew);
    scan_kernel<<<1, 1024>>>();
    fill_kernel<<<(EE + 255) / 256, 256>>>(row, col, ew);

    const float* h = x;      // layer input
    float* pOut = bufA;      // layer output (ping-pong)
    float* pAlt = bufB;

    for (int l = 0; l < 6; l++) {
        int Fin = DIMS[l], Fout = DIMS[l + 1];
        int FV = Fin / 4;
        int npb = 256 / FV;
        unsigned gblocks = (unsigned)((NN + npb - 1) / npb);

        // Tx1 = L h
        spmm_gather<<<gblocks, 256>>>((const float4*)h, nullptr, 1.f, 0.f,
                                      (float4*)t1, FV, npb);
        // Tx2 = 2 L Tx1 - h
        spmm_gather<<<gblocks, 256>>>((const float4*)t1, (const float4*)h, 2.f, -1.f,
                                      (float4*)t2, FV, npb);

        // out = softplus(h@W0 + Tx1@W1 + Tx2@W2 + b)
        if (Fout >= 128) {
            dim3 grid((NN + 127) / 128, Fout / 128);
            gemm3_tc<<<grid, 256>>>(h, t1, t2, Wp[l], bp[l], pOut, Fin, Fout);
        } else {
            dim3 grid((NN + 63) / 64, (Fout + 63) / 64);
            gemm3_small<<<grid, 256>>>(h, t1, t2, Wp[l], bp[l], pOut, Fin, Fout);
        }

        h = pOut;
        float* tmp = pOut; pOut = pAlt; pAlt = tmp;
    }

    // final FC 512 -> 3
    fc_kernel<<<((long)NN * 32 + 255) / 256, 256>>>(h, fcw, fcb, out);
}

// round 7
// speedup vs baseline: 3.6123x; 1.1778x over previous
#include <cuda_runtime.h>
#include <math.h>
#include <stdint.h>

#define NN 30000
#define EE 480000

// dims per layer: input 128 -> 16 -> 32 -> 64 -> 128 -> 256 -> 512
static const int DIMS[7] = {128, 16, 32, 64, 128, 256, 512};

// Scratch (static __device__ arrays; no allocations allowed)
__device__ float g_bufA[(size_t)NN * 512];
__device__ float g_bufB[(size_t)NN * 512];
__device__ float g_t1[(size_t)NN * 256];
__device__ float g_t2[(size_t)NN * 256];
__device__ float g_deg[NN];
__device__ int   g_cnt[NN];
__device__ int   g_ptr[NN + 1];
__device__ int   g_cur[NN];
__device__ int   g_srcidx[EE];     // row indices sorted by destination column
__device__ float g_wsort[EE];      // normalized edge weights sorted by destination column
__device__ float g_wrnd[516096];   // tf32-rounded weights for tc layers (3,4,5)

// ---------------------------------------------------------------------------
__device__ __forceinline__ float rnd_tf32(float x) {
    uint32_t u;
    asm("cvt.rna.tf32.f32 %0, %1;" : "=r"(u) : "f"(x));
    return __uint_as_float(u);
}

__device__ __forceinline__ float softplusf(float x) {
    return fmaxf(x, 0.f) + log1pf(__expf(-fabsf(x)));
}

__device__ __forceinline__ uint32_t smem_u32(const void* p) {
    return (uint32_t)__cvta_generic_to_shared(p);
}

__device__ __forceinline__ void cp_async16(uint32_t dst, const void* src, int srcBytes) {
    asm volatile("cp.async.ca.shared.global [%0], [%1], 16, %2;\n"
                 :: "r"(dst), "l"(src), "r"(srcBytes));
}

__device__ __forceinline__ void mma_tf32(float (&d)[4], const uint32_t (&a)[4],
                                         const uint32_t (&b)[2]) {
    asm volatile(
        "mma.sync.aligned.m16n8k8.row.col.f32.tf32.tf32.f32 "
        "{%0,%1,%2,%3},{%4,%5,%6,%7},{%8,%9},{%0,%1,%2,%3};"
        : "+f"(d[0]), "+f"(d[1]), "+f"(d[2]), "+f"(d[3])
        : "r"(a[0]), "r"(a[1]), "r"(a[2]), "r"(a[3]), "r"(b[0]), "r"(b[1]));
}

// ---------------------------------------------------------------------------
// Pass 1: deg[row[e]] += ew[e];  cnt[col[e]] += 1
__global__ void deg_count_kernel(const int* __restrict__ row, const int* __restrict__ col,
                                 const float* __restrict__ ew) {
    int e = blockIdx.x * blockDim.x + threadIdx.x;
    if (e < EE) {
        atomicAdd(&g_deg[row[e]], ew[e]);
        atomicAdd(&g_cnt[col[e]], 1);
    }
}

// Pass 2: exclusive prefix sum of cnt -> ptr, cur. Single block, shuffle scan.
__global__ void scan_kernel() {
    const int tid = threadIdx.x;
    const int lane = tid & 31, wid = tid >> 5;
    __shared__ int wsum[32];
    __shared__ int s_off;
    if (tid == 0) s_off = 0;
    __syncthreads();
    for (int base = 0; base < NN; base += 1024) {
        int i = base + tid;
        int v = (i < NN) ? g_cnt[i] : 0;
        int incl = v;
#pragma unroll
        for (int o = 1; o < 32; o <<= 1) {
            int t = __shfl_up_sync(0xffffffffu, incl, o);
            if (lane >= o) incl += t;
        }
        if (lane == 31) wsum[wid] = incl;
        __syncthreads();
        if (wid == 0) {
            int s = wsum[lane];
            int inc2 = s;
#pragma unroll
            for (int o = 1; o < 32; o <<= 1) {
                int t = __shfl_up_sync(0xffffffffu, inc2, o);
                if (lane >= o) inc2 += t;
            }
            wsum[lane] = inc2 - s;   // exclusive warp prefix
        }
        __syncthreads();
        int excl = s_off + wsum[wid] + incl - v;
        if (i < NN) { g_ptr[i] = excl; g_cur[i] = excl; }
        __syncthreads();
        if (tid == 1023) s_off += wsum[31] + incl;   // chunk total
        __syncthreads();
    }
    if (tid == 0) g_ptr[NN] = s_off;
}

// Pass 3: scatter edges into CSC slots; compute normalized weight on the way
__global__ void fill_kernel(const int* __restrict__ row, const int* __restrict__ col,
                            const float* __restrict__ ew) {
    int e = blockIdx.x * blockDim.x + threadIdx.x;
    if (e < EE) {
        int c = col[e];
        int p = atomicAdd(&g_cur[c], 1);
        int r = row[e];
        g_srcidx[p] = r;
        float d = g_deg[r];
        g_wsort[p] = (d > 0.f) ? (-ew[e] / d) : 0.f;   // -(2/lmax) * ew / deg, lmax=2
    }
}

// one-shot: tf32-round a weight tensor
__global__ void roundw_kernel(const float* __restrict__ src, float* __restrict__ dst, int n) {
    int i = blockIdx.x * blockDim.x + threadIdx.x;
    if (i < n) dst[i] = rnd_tf32(src[i]);
}

// ---------------------------------------------------------------------------
// Gather SpMM: dst[c] = scale * sum_{e in col c} w[e]*src[srcidx[e]]  (+ addscale*addsrc[c])
// x-lanes = FV float4-lanes of the feature dim; whole warp works one node when FV>=32.
__global__ void spmm_gather(const float4* __restrict__ src, const float4* __restrict__ addsrc,
                            float scale, float addscale, float4* __restrict__ dst,
                            int FV, int npb, int roundOut) {
    int ty = threadIdx.x / FV;
    int tx = threadIdx.x - ty * FV;
    int c = blockIdx.x * npb + ty;
    if (c >= NN) return;
    int beg = g_ptr[c], end = g_ptr[c + 1];
    float4 acc = make_float4(0.f, 0.f, 0.f, 0.f);

    if (FV >= 32) {
        // whole warp = one node: batch-load edges, shuffle-broadcast
        int lane = threadIdx.x & 31;
        for (int eb = beg; eb < end; eb += 32) {
            int n = end - eb; if (n > 32) n = 32;
            int r_l = 0; float w_l = 0.f;
            if (lane < n) { r_l = g_srcidx[eb + lane]; w_l = g_wsort[eb + lane]; }
            for (int j = 0; j < n; j++) {
                int r = __shfl_sync(0xffffffffu, r_l, j);
                float w = __shfl_sync(0xffffffffu, w_l, j);
                float4 v = src[(size_t)r * FV + tx];
                acc.x = fmaf(w, v.x, acc.x);
                acc.y = fmaf(w, v.y, acc.y);
                acc.z = fmaf(w, v.z, acc.z);
                acc.w = fmaf(w, v.w, acc.w);
            }
        }
    } else {
        for (int e = beg; e < end; e++) {
            int r = g_srcidx[e];
            float w = g_wsort[e];
            float4 v = src[(size_t)r * FV + tx];
            acc.x = fmaf(w, v.x, acc.x);
            acc.y = fmaf(w, v.y, acc.y);
            acc.z = fmaf(w, v.z, acc.z);
            acc.w = fmaf(w, v.w, acc.w);
        }
    }

    float4 o = make_float4(scale * acc.x, scale * acc.y, scale * acc.z, scale * acc.w);
    if (addsrc) {
        float4 a = addsrc[(size_t)c * FV + tx];
        o.x = fmaf(addscale, a.x, o.x);
        o.y = fmaf(addscale, a.y, o.y);
        o.z = fmaf(addscale, a.z, o.z);
        o.w = fmaf(addscale, a.w, o.w);
    }
    if (roundOut) {
        o.x = rnd_tf32(o.x); o.y = rnd_tf32(o.y);
        o.z = rnd_tf32(o.z); o.w = rnd_tf32(o.w);
    }
    dst[(size_t)c * FV + tx] = o;
}

// ---------------------------------------------------------------------------
// Tensor-core GEMM (tf32, cp.async double-buffered):
// out = softplus([A0|A1|A2] @ [W0;W1;W2] + bias)
// 128x128x16 block tile, 8 warps, each warp 64x32. Inputs (A* and W) must be
// tf32-pre-rounded fp32 (HW truncation in HMMA is then exact).
// Requires Fout % 128 == 0, Fin % 16 == 0.
__global__ __launch_bounds__(256) void gemm3_tc(
        const float* __restrict__ A0, const float* __restrict__ A1,
        const float* __restrict__ A2, const float* __restrict__ W,
        const float* __restrict__ bias, float* __restrict__ out,
        int Fin, int Fout, int roundOut) {
    constexpr int BK = 16;
    constexpr int SAS = 20;    // sA [m][k] word stride: bank=(4m+k)%32 over frag lanes -> CF
    constexpr int SBS = 136;   // sB [k][n] word stride: bank=(8k+n)%32 over frag lanes -> CF
    constexpr int ASZ = 128 * SAS;   // 2560 words / stage
    constexpr int BSZ = BK * SBS;    // 2176 words / stage
    __shared__ __align__(16) uint32_t sA[2][ASZ];
    __shared__ __align__(16) uint32_t sB[2][BSZ];

    const int tid = threadIdx.x;
    const int lane = tid & 31;
    const int warp = tid >> 5;
    const int warp_m = warp & 1;    // 0..1 -> 64 rows each
    const int warp_n = warp >> 1;   // 0..3 -> 32 cols each
    const int bm = blockIdx.x * 128, bn = blockIdx.y * 128;
    const int grp = lane >> 2;      // 0..7
    const int tig = lane & 3;       // 0..3

    const uint32_t sA_base = smem_u32(&sA[0][0]);
    const uint32_t sB_base = smem_u32(&sB[0][0]);

    float acc[4][4][4];
#pragma unroll
    for (int i = 0; i < 4; i++)
#pragma unroll
        for (int j = 0; j < 4; j++)
#pragma unroll
            for (int v = 0; v < 4; v++) acc[i][j][v] = 0.f;

    const float* As[3] = {A0, A1, A2};
    const int KT = 3 * Fin;
    const int T = KT / BK;

    // per-thread cp.async chunk mappings (constant across tiles)
    const int am0 = tid >> 2;                 // A: m for chunk 0 (chunk1: +64)
    const int akc = (tid & 3) * 4;            // A: k offset
    const int bk0 = tid >> 5;                 // B: k for chunk 0 (chunk1: +8)
    const int bnc = (tid & 31) * 4;           // B: n offset

    auto load_tile = [&](int t, int st) {
        int k0 = t * BK;
        int seg = k0 / Fin;
        int koff = k0 - seg * Fin;
        const float* Ap = As[seg];
        uint32_t da = sA_base + st * (ASZ * 4);
        uint32_t db = sB_base + st * (BSZ * 4);
#pragma unroll
        for (int i = 0; i < 2; i++) {
            int m = am0 + i * 64;
            int gm = bm + m;
            const float* src = Ap + (size_t)gm * Fin + koff + akc;
            cp_async16(da + (m * SAS + akc) * 4, src, gm < NN ? 16 : 0);
        }
#pragma unroll
        for (int i = 0; i < 2; i++) {
            int k = bk0 + i * 8;
            const float* src = W + (size_t)(k0 + k) * Fout + bn + bnc;
            cp_async16(db + (k * SBS + bnc) * 4, src, 16);
        }
        asm volatile("cp.async.commit_group;\n" ::: "memory");
    };

    load_tile(0, 0);

    for (int t = 0; t < T; t++) {
        int st = t & 1;
        if (t + 1 < T) {
            load_tile(t + 1, (t + 1) & 1);
            asm volatile("cp.async.wait_group 1;\n" ::: "memory");
        } else {
            asm volatile("cp.async.wait_group 0;\n" ::: "memory");
        }
        __syncthreads();

        const uint32_t* pA = sA[st];
        const uint32_t* pB = sB[st];
#pragma unroll
        for (int ks = 0; ks < BK; ks += 8) {
            uint32_t af[4][4];
            uint32_t bf[4][2];
#pragma unroll
            for (int mf = 0; mf < 4; mf++) {
                int m = warp_m * 64 + mf * 16 + grp;
                af[mf][0] = pA[m * SAS + ks + tig];
                af[mf][1] = pA[(m + 8) * SAS + ks + tig];
                af[mf][2] = pA[m * SAS + ks + tig + 4];
                af[mf][3] = pA[(m + 8) * SAS + ks + tig + 4];
            }
#pragma unroll
            for (int nf = 0; nf < 4; nf++) {
                int n = warp_n * 32 + nf * 8 + grp;
                bf[nf][0] = pB[(ks + tig) * SBS + n];
                bf[nf][1] = pB[(ks + tig + 4) * SBS + n];
            }
#pragma unroll
            for (int mf = 0; mf < 4; mf++)
#pragma unroll
                for (int nf = 0; nf < 4; nf++)
                    mma_tf32(acc[mf][nf], af[mf], bf[nf]);
        }
        __syncthreads();
    }

    // Epilogue
#pragma unroll
    for (int mf = 0; mf < 4; mf++) {
        int m0 = bm + warp_m * 64 + mf * 16 + grp;
#pragma unroll
        for (int nf = 0; nf < 4; nf++) {
            int n0 = bn + warp_n * 32 + nf * 8 + 2 * tig;
            float b0 = bias[n0], b1 = bias[n0 + 1];
            if (m0 < NN) {
                float v0 = softplusf(acc[mf][nf][0] + b0);
                float v1 = softplusf(acc[mf][nf][1] + b1);
                if (roundOut) { v0 = rnd_tf32(v0); v1 = rnd_tf32(v1); }
                float* d = out + (size_t)m0 * Fout + n0;
                d[0] = v0; d[1] = v1;
            }
            if (m0 + 8 < NN) {
                float v0 = softplusf(acc[mf][nf][2] + b0);
                float v1 = softplusf(acc[mf][nf][3] + b1);
                if (roundOut) { v0 = rnd_tf32(v0); v1 = rnd_tf32(v1); }
                float* d = out + (size_t)(m0 + 8) * Fout + n0;
                d[0] = v0; d[1] = v1;
            }
        }
    }
}

// ---------------------------------------------------------------------------
// Small GEMM, BN == Fout exactly (16/32/64). BM=64, BK=8, 256 threads,
// 16 col-threads x 16 row-threads, thread tile 4 x (BN/16).
template<int BN>
__global__ void gemm3_small_t(const float* __restrict__ A0, const float* __restrict__ A1,
                              const float* __restrict__ A2, const float* __restrict__ W,
                              const float* __restrict__ bias, float* __restrict__ out,
                              int Fin, int roundOut) {
    constexpr int BM = 64, BK = 8;
    constexpr int TN = BN / 16;
    __shared__ float sA[BK][BM];
    __shared__ float sB[BK][BN];
    const int bm = blockIdx.x * BM;
    const int tid = threadIdx.x;
    const int tx = tid & 15, ty = tid >> 4;

    float acc[4][TN];
#pragma unroll
    for (int i = 0; i < 4; i++)
#pragma unroll
        for (int j = 0; j < TN; j++) acc[i][j] = 0.f;

    const float* As[3] = {A0, A1, A2};
    for (int k = 0; k < 3; k++) {
        const float* A = As[k];
        const float* Wk = W + (size_t)k * Fin * BN;
        for (int i0 = 0; i0 < Fin; i0 += BK) {
#pragma unroll
            for (int l = 0; l < 2; l++) {
                int idx = tid + l * 256;
                int mm = idx >> 3, kk = idx & 7;
                int m = bm + mm;
                sA[kk][mm] = (m < NN) ? A[(size_t)m * Fin + i0 + kk] : 0.f;
            }
            for (int idx = tid; idx < BK * BN; idx += 256) {
                int kk = idx / BN, nn = idx - kk * BN;
                sB[kk][nn] = Wk[(size_t)(i0 + kk) * BN + nn];
            }
            __syncthreads();
#pragma unroll
            for (int kk = 0; kk < BK; kk++) {
                float a[4], b[TN];
#pragma unroll
                for (int i = 0; i < 4; i++) a[i] = sA[kk][ty * 4 + i];
#pragma unroll
                for (int j = 0; j < TN; j++) b[j] = sB[kk][tx * TN + j];
#pragma unroll
                for (int i = 0; i < 4; i++)
#pragma unroll
                    for (int j = 0; j < TN; j++) acc[i][j] = fmaf(a[i], b[j], acc[i][j]);
            }
            __syncthreads();
        }
    }

#pragma unroll
    for (int i = 0; i < 4; i++) {
        int m = bm + ty * 4 + i;
        if (m >= NN) continue;
#pragma unroll
        for (int j = 0; j < TN; j++) {
            int n = tx * TN + j;
            float v = softplusf(acc[i][j] + bias[n]);
            if (roundOut) v = rnd_tf32(v);
            out[(size_t)m * BN + n] = v;
        }
    }
}

// final FC: out[n][0:3] = h[n][0:512] @ fc_w (512x3) + fc_b; one warp per node
__global__ void fc_kernel(const float* __restrict__ h, const float* __restrict__ fw,
                          const float* __restrict__ fb, float* __restrict__ out) {
    int gw = (blockIdx.x * blockDim.x + threadIdx.x) >> 5;
    int lane = threadIdx.x & 31;
    if (gw >= NN) return;
    const float* hr = h + (size_t)gw * 512;
    float a0 = 0.f, a1 = 0.f, a2 = 0.f;
    for (int i = lane; i < 512; i += 32) {
        float v = hr[i];
        a0 = fmaf(v, fw[i * 3 + 0], a0);
        a1 = fmaf(v, fw[i * 3 + 1], a1);
        a2 = fmaf(v, fw[i * 3 + 2], a2);
    }
#pragma unroll
    for (int o = 16; o > 0; o >>= 1) {
        a0 += __shfl_down_sync(0xffffffffu, a0, o);
        a1 += __shfl_down_sync(0xffffffffu, a1, o);
        a2 += __shfl_down_sync(0xffffffffu, a2, o);
    }
    if (lane == 0) {
        out[gw * 3 + 0] = a0 + fb[0];
        out[gw * 3 + 1] = a1 + fb[1];
        out[gw * 3 + 2] = a2 + fb[2];
    }
}

// ---------------------------------------------------------------------------

extern "C" void kernel_launch(void* const* d_in, const int* in_sizes, int n_in,
                              void* d_out, int out_size) {
    (void)in_sizes; (void)n_in; (void)out_size;

    const float* x   = (const float*)d_in[0];
    const int*   ei  = (const int*)d_in[1];   // (2, E)
    const float* ew  = (const float*)d_in[2];
    const float* Wp[6];
    const float* bp[6];
    for (int l = 0; l < 6; l++) {
        Wp[l] = (const float*)d_in[4 + 2 * l];
        bp[l] = (const float*)d_in[5 + 2 * l];
    }
    const float* fcw = (const float*)d_in[16];
    const float* fcb = (const float*)d_in[17];
    float* out = (float*)d_out;

    float *bufA, *bufB, *t1, *t2, *deg, *wrnd;
    int *cnt;
    cudaGetSymbolAddress((void**)&bufA, g_bufA);
    cudaGetSymbolAddress((void**)&bufB, g_bufB);
    cudaGetSymbolAddress((void**)&t1,   g_t1);
    cudaGetSymbolAddress((void**)&t2,   g_t2);
    cudaGetSymbolAddress((void**)&deg,  g_deg);
    cudaGetSymbolAddress((void**)&cnt,  g_cnt);
    cudaGetSymbolAddress((void**)&wrnd, g_wrnd);

    const int* row = ei;
    const int* col = ei + EE;

    // tf32-round weights of the tensor-core layers (3,4,5)
    const int woff[3] = {0, 24576, 122880};          // 3*64*128, +3*128*256
    const int wlen[3] = {24576, 98304, 393216};
    for (int i = 0; i < 3; i++)
        roundw_kernel<<<(wlen[i] + 255) / 256, 256>>>(Wp[3 + i], wrnd + woff[i], wlen[i]);

    // CSC build (fresh each call)
    cudaMemsetAsync(deg, 0, NN * sizeof(float));
    cudaMemsetAsync(cnt, 0, NN * sizeof(int));
    deg_count_kernel<<<(EE + 255) / 256, 256>>>(row, col, ew);
    scan_kernel<<<1, 1024>>>();
    fill_kernel<<<(EE + 255) / 256, 256>>>(row, col, ew);

    const float* h = x;      // layer input
    float* pOut = bufA;      // layer output (ping-pong)
    float* pAlt = bufB;

    for (int l = 0; l < 6; l++) {
        int Fin = DIMS[l], Fout = DIMS[l + 1];
        int FV = Fin / 4;
        int npb = 256 / FV;
        unsigned gblocks = (unsigned)((NN + npb - 1) / npb);
        int rnd_sp = (l >= 3) ? 1 : 0;            // t1/t2 feed tc GEMM for l>=3

        // Tx1 = L h
        spmm_gather<<<gblocks, 256>>>((const float4*)h, nullptr, 1.f, 0.f,
                                      (float4*)t1, FV, npb, rnd_sp);
        // Tx2 = 2 L Tx1 - h
        spmm_gather<<<gblocks, 256>>>((const float4*)t1, (const float4*)h, 2.f, -1.f,
                                      (float4*)t2, FV, npb, rnd_sp);

        // out = softplus(h@W0 + Tx1@W1 + Tx2@W2 + b)
        if (Fout >= 128) {
            int rnd_out = (l < 5) ? 1 : 0;        // output feeds next tc layer
            dim3 grid((NN + 127) / 128, Fout / 128);
            gemm3_tc<<<grid, 256>>>(h, t1, t2, wrnd + woff[l - 3], bp[l], pOut,
                                    Fin, Fout, rnd_out);
        } else {
            int rnd_out = (l == 2) ? 1 : 0;       // h3 feeds tc layer 3
            unsigned gx = (NN + 63) / 64;
            if (Fout == 16)
                gemm3_small_t<16><<<gx, 256>>>(h, t1, t2, Wp[l], bp[l], pOut, Fin, rnd_out);
            else if (Fout == 32)
                gemm3_small_t<32><<<gx, 256>>>(h, t1, t2, Wp[l], bp[l], pOut, Fin, rnd_out);
            else
                gemm3_small_t<64><<<gx, 256>>>(h, t1, t2, Wp[l], bp[l], pOut, Fin, rnd_out);
        }

        h = pOut;
        float* tmp = pOut; pOut = pAlt; pAlt = tmp;
    }

    // final FC 512 -> 3
    fc_kernel<<<((long)NN * 32 + 255) / 256, 256>>>(h, fcw, fcb, out);
}

// round 10
// speedup vs baseline: 4.9047x; 1.3578x over previous
#include <cuda_runtime.h>
#include <cuda_fp16.h>
#include <math.h>
#include <stdint.h>

#define NN 30000
#define EE 480000

// dims per layer: input 128 -> 16 -> 32 -> 64 -> 128 -> 256 -> 512
static const int DIMS[7] = {128, 16, 32, 64, 128, 256, 512};

// Scratch (static __device__ arrays; no allocations allowed)
__device__ float g_bufA[(size_t)NN * 64];        // fp32 ping-pong for layers 0-1
__device__ float g_bufB[(size_t)NN * 64];
__device__ float g_t1f[(size_t)NN * 128];        // fp32 Tx for layers 0-2
__device__ float g_t2f[(size_t)NN * 128];
__device__ uint4 g_hA[(size_t)NN * 512 / 8];     // fp16 ping-pong for layers 3-5
__device__ uint4 g_hB[(size_t)NN * 512 / 8];
__device__ uint4 g_t1h[(size_t)NN * 256 / 8];    // fp16 Tx for layers 3-5
__device__ uint4 g_t2h[(size_t)NN * 256 / 8];
__device__ uint4 g_wh[516096 / 8];               // fp16 transposed weights, tc layers
__device__ float g_deg[NN];
__device__ int   g_cnt[NN];
__device__ int   g_ptr[NN + 1];
__device__ int   g_cur[NN];
__device__ int   g_srcidx[EE];
__device__ float g_wsort[EE];

// ---------------------------------------------------------------------------
__device__ __forceinline__ float softplusf(float x) {
    return fmaxf(x, 0.f) + log1pf(__expf(-fabsf(x)));
}

__device__ __forceinline__ uint32_t smem_u32(const void* p) {
    return (uint32_t)__cvta_generic_to_shared(p);
}

__device__ __forceinline__ void cp_async16(uint32_t dst, const void* src, int srcBytes) {
    asm volatile("cp.async.ca.shared.global [%0], [%1], 16, %2;\n"
                 :: "r"(dst), "l"(src), "r"(srcBytes));
}

__device__ __forceinline__ void ldsm4(uint32_t (&r)[4], uint32_t addr) {
    asm volatile("ldmatrix.sync.aligned.m8n8.x4.shared.b16 {%0,%1,%2,%3}, [%4];"
                 : "=r"(r[0]), "=r"(r[1]), "=r"(r[2]), "=r"(r[3]) : "r"(addr));
}

__device__ __forceinline__ void mma_f16(float (&d)[4], const uint32_t (&a)[4],
                                        const uint32_t* b) {
    asm volatile(
        "mma.sync.aligned.m16n8k16.row.col.f32.f16.f16.f32 "
        "{%0,%1,%2,%3},{%4,%5,%6,%7},{%8,%9},{%0,%1,%2,%3};"
        : "+f"(d[0]), "+f"(d[1]), "+f"(d[2]), "+f"(d[3])
        : "r"(a[0]), "r"(a[1]), "r"(a[2]), "r"(a[3]), "r"(b[0]), "r"(b[1]));
}

// ---------------------------------------------------------------------------
// CSC build
__global__ void deg_count_kernel(const int* __restrict__ row, const int* __restrict__ col,
                                 const float* __restrict__ ew) {
    int e = blockIdx.x * blockDim.x + threadIdx.x;
    if (e < EE) {
        atomicAdd(&g_deg[row[e]], ew[e]);
        atomicAdd(&g_cnt[col[e]], 1);
    }
}

__global__ void scan_kernel() {
    const int tid = threadIdx.x;
    const int lane = tid & 31, wid = tid >> 5;
    __shared__ int wsum[32];
    __shared__ int s_off;
    if (tid == 0) s_off = 0;
    __syncthreads();
    for (int base = 0; base < NN; base += 1024) {
        int i = base + tid;
        int v = (i < NN) ? g_cnt[i] : 0;
        int incl = v;
#pragma unroll
        for (int o = 1; o < 32; o <<= 1) {
            int t = __shfl_up_sync(0xffffffffu, incl, o);
            if (lane >= o) incl += t;
        }
        if (lane == 31) wsum[wid] = incl;
        __syncthreads();
        if (wid == 0) {
            int s = wsum[lane];
            int inc2 = s;
#pragma unroll
            for (int o = 1; o < 32; o <<= 1) {
                int t = __shfl_up_sync(0xffffffffu, inc2, o);
                if (lane >= o) inc2 += t;
            }
            wsum[lane] = inc2 - s;
        }
        __syncthreads();
        int excl = s_off + wsum[wid] + incl - v;
        if (i < NN) { g_ptr[i] = excl; g_cur[i] = excl; }
        __syncthreads();
        if (tid == 1023) s_off += wsum[31] + incl;
        __syncthreads();
    }
    if (tid == 0) g_ptr[NN] = s_off;
}

__global__ void fill_kernel(const int* __restrict__ row, const int* __restrict__ col,
                            const float* __restrict__ ew) {
    int e = blockIdx.x * blockDim.x + threadIdx.x;
    if (e < EE) {
        int c = col[e];
        int p = atomicAdd(&g_cur[c], 1);
        int r = row[e];
        g_srcidx[p] = r;
        float d = g_deg[r];
        g_wsort[p] = (d > 0.f) ? (-ew[e] / d) : 0.f;
    }
}

// one-shot: convert W (3,Fin,Fout) fp32 -> Wt (3,Fout,Fin) fp16 (transposed)
__global__ void convw_kernel(const float* __restrict__ src, __half* __restrict__ dst,
                             int Fin, int Fout) {
    int idx = blockIdx.x * blockDim.x + threadIdx.x;
    int tot = 3 * Fin * Fout;
    if (idx < tot) {
        int s = idx / (Fin * Fout);
        int rem = idx - s * Fin * Fout;
        int k = rem / Fout;
        int n = rem - k * Fout;
        dst[(size_t)s * Fin * Fout + (size_t)n * Fin + k] = __float2half_rn(src[idx]);
    }
}

// ---------------------------------------------------------------------------
// fp32 gather SpMM (layers 0-2)
__global__ void spmm_gather(const float4* __restrict__ src, const float4* __restrict__ addsrc,
                            float scale, float addscale, float4* __restrict__ dst,
                            int FV, int npb) {
    int ty = threadIdx.x / FV;
    int tx = threadIdx.x - ty * FV;
    int c = blockIdx.x * npb + ty;
    if (c >= NN) return;
    int beg = g_ptr[c], end = g_ptr[c + 1];
    float4 acc = make_float4(0.f, 0.f, 0.f, 0.f);

    if (FV >= 32) {
        int lane = threadIdx.x & 31;
        for (int eb = beg; eb < end; eb += 32) {
            int n = end - eb; if (n > 32) n = 32;
            int r_l = 0; float w_l = 0.f;
            if (lane < n) { r_l = g_srcidx[eb + lane]; w_l = g_wsort[eb + lane]; }
            for (int j = 0; j < n; j++) {
                int r = __shfl_sync(0xffffffffu, r_l, j);
                float w = __shfl_sync(0xffffffffu, w_l, j);
                float4 v = src[(size_t)r * FV + tx];
                acc.x = fmaf(w, v.x, acc.x);
                acc.y = fmaf(w, v.y, acc.y);
                acc.z = fmaf(w, v.z, acc.z);
                acc.w = fmaf(w, v.w, acc.w);
            }
        }
    } else {
        for (int e = beg; e < end; e++) {
            int r = g_srcidx[e];
            float w = g_wsort[e];
            float4 v = src[(size_t)r * FV + tx];
            acc.x = fmaf(w, v.x, acc.x);
            acc.y = fmaf(w, v.y, acc.y);
            acc.z = fmaf(w, v.z, acc.z);
            acc.w = fmaf(w, v.w, acc.w);
        }
    }

    float4 o = make_float4(scale * acc.x, scale * acc.y, scale * acc.z, scale * acc.w);
    if (addsrc) {
        float4 a = addsrc[(size_t)c * FV + tx];
        o.x = fmaf(addscale, a.x, o.x);
        o.y = fmaf(addscale, a.y, o.y);
        o.z = fmaf(addscale, a.z, o.z);
        o.w = fmaf(addscale, a.w, o.w);
    }
    dst[(size_t)c * FV + tx] = o;
}

// fp16 gather SpMM (layers 3-5). FV = Fin/8 (uint4 = 8 halves). fp32 accumulate.
__global__ void spmm_gather_h(const uint4* __restrict__ src, const uint4* __restrict__ addsrc,
                              float scale, float addscale, uint4* __restrict__ dst,
                              int FV, int npb) {
    int ty = threadIdx.x / FV;
    int tx = threadIdx.x - ty * FV;
    int c = blockIdx.x * npb + ty;
    if (c >= NN) return;
    int beg = g_ptr[c], end = g_ptr[c + 1];
    float2 acc[4];
#pragma unroll
    for (int q = 0; q < 4; q++) acc[q] = make_float2(0.f, 0.f);

    if (FV >= 32) {
        int lane = threadIdx.x & 31;
        for (int eb = beg; eb < end; eb += 32) {
            int n = end - eb; if (n > 32) n = 32;
            int r_l = 0; float w_l = 0.f;
            if (lane < n) { r_l = g_srcidx[eb + lane]; w_l = g_wsort[eb + lane]; }
            for (int j = 0; j < n; j++) {
                int r = __shfl_sync(0xffffffffu, r_l, j);
                float w = __shfl_sync(0xffffffffu, w_l, j);
                uint4 v = src[(size_t)r * FV + tx];
                const __half2* hp = (const __half2*)&v;
#pragma unroll
                for (int q = 0; q < 4; q++) {
                    float2 f = __half22float2(hp[q]);
                    acc[q].x = fmaf(w, f.x, acc[q].x);
                    acc[q].y = fmaf(w, f.y, acc[q].y);
                }
            }
        }
    } else {
        for (int e = beg; e < end; e++) {
            int r = g_srcidx[e];
            float w = g_wsort[e];
            uint4 v = src[(size_t)r * FV + tx];
            const __half2* hp = (const __half2*)&v;
#pragma unroll
            for (int q = 0; q < 4; q++) {
                float2 f = __half22float2(hp[q]);
                acc[q].x = fmaf(w, f.x, acc[q].x);
                acc[q].y = fmaf(w, f.y, acc[q].y);
            }
        }
    }

    uint4 r;
    __half2* rp = (__half2*)&r;
    if (addsrc) {
        uint4 a = addsrc[(size_t)c * FV + tx];
        const __half2* ap = (const __half2*)&a;
#pragma unroll
        for (int q = 0; q < 4; q++) {
            float2 af = __half22float2(ap[q]);
            float ox = fmaf(addscale, af.x, scale * acc[q].x);
            float oy = fmaf(addscale, af.y, scale * acc[q].y);
            rp[q] = __floats2half2_rn(ox, oy);
        }
    } else {
#pragma unroll
        for (int q = 0; q < 4; q++)
            rp[q] = __floats2half2_rn(scale * acc[q].x, scale * acc[q].y);
    }
    dst[(size_t)c * FV + tx] = r;
}

// ---------------------------------------------------------------------------
// fp16 tensor-core GEMM: out = softplus([A0|A1|A2] @ [W0;W1;W2] + bias), fp16 in/out,
// fp32 accumulate. 128x128x32 block tile, cp.async double buffer, ldmatrix fragments.
// Wt is (3, Fout, Fin) fp16 (transposed). Requires Fout%128==0, Fin%32==0.
__global__ __launch_bounds__(256) void gemm3_tc_h(
        const __half* __restrict__ A0, const __half* __restrict__ A1,
        const __half* __restrict__ A2, const __half* __restrict__ Wt,
        const float* __restrict__ bias, __half* __restrict__ out,
        int Fin, int Fout) {
    constexpr int BK = 32;
    constexpr int SKA = 40;            // halves; row stride 80B -> ldmatrix conflict-free
    constexpr int SKB = 40;
    constexpr int ASZ = 128 * SKA;     // halves per stage
    constexpr int BSZ = 128 * SKB;
    __shared__ __align__(16) __half sA[2][ASZ];
    __shared__ __align__(16) __half sB[2][BSZ];

    const int tid = threadIdx.x;
    const int lane = tid & 31;
    const int warp = tid >> 5;
    const int warp_m = warp & 1;       // 64 rows each
    const int warp_n = warp >> 1;      // 32 cols each
    const int bm = blockIdx.x * 128, bn = blockIdx.y * 128;
    const int grp = lane >> 2;
    const int tig = lane & 3;

    const uint32_t sA_base = smem_u32(&sA[0][0]);
    const uint32_t sB_base = smem_u32(&sB[0][0]);

    // ldmatrix lane offsets
    const int a_row = (lane & 7) + ((lane >> 3) & 1) * 8;   // tiles 1,3: +8 rows
    const int a_kof = ((lane >> 4) & 1) * 8;                // tiles 2,3: +8 k
    const int b_row = (lane & 7) + ((lane >> 4) & 1) * 8;   // tiles 2,3: +8 n
    const int b_kof = ((lane >> 3) & 1) * 8;                // tiles 1,3: +8 k

    float acc[4][4][4];
#pragma unroll
    for (int i = 0; i < 4; i++)
#pragma unroll
        for (int j = 0; j < 4; j++)
#pragma unroll
            for (int v = 0; v < 4; v++) acc[i][j][v] = 0.f;

    const __half* As[3] = {A0, A1, A2};
    const int KT = 3 * Fin;
    const int T = KT / BK;

    auto load_tile = [&](int t, int st) {
        int k0 = t * BK;
        int seg = k0 / Fin;
        int koff = k0 - seg * Fin;
        const __half* Ap = As[seg];
        const __half* Bp = Wt + (size_t)seg * Fin * Fout;
        uint32_t da = sA_base + st * (ASZ * 2);
        uint32_t db = sB_base + st * (BSZ * 2);
        // Tile = 128 rows x 32 halves = 512 16B-chunks per operand; 256 threads x 2 chunks.
#pragma unroll
        for (int i = 0; i < 2; i++) {
            int chunk = tid + i * 256;
            int r = chunk >> 2;              // 0..127
            int kc = (chunk & 3) * 8;        // 0,8,16,24 halves
            int gm = bm + r;
            const __half* srcA = Ap + (size_t)gm * Fin + koff + kc;
            cp_async16(da + (r * SKA + kc) * 2, srcA, gm < NN ? 16 : 0);
            int gn = bn + r;                 // always < Fout (grid.y = Fout/128)
            const __half* srcB = Bp + (size_t)gn * Fin + koff + kc;
            cp_async16(db + (r * SKB + kc) * 2, srcB, 16);
        }
        asm volatile("cp.async.commit_group;\n" ::: "memory");
    };

    load_tile(0, 0);

    for (int t = 0; t < T; t++) {
        int st = t & 1;
        if (t + 1 < T) {
            load_tile(t + 1, (t + 1) & 1);
            asm volatile("cp.async.wait_group 1;\n" ::: "memory");
        } else {
            asm volatile("cp.async.wait_group 0;\n" ::: "memory");
        }
        __syncthreads();

        uint32_t aab = sA_base + st * (ASZ * 2);
        uint32_t bbb = sB_base + st * (BSZ * 2);
#pragma unroll
        for (int ks = 0; ks < BK; ks += 16) {
            uint32_t af[4][4];
#pragma unroll
            for (int mf = 0; mf < 4; mf++) {
                int m = warp_m * 64 + mf * 16 + a_row;
                ldsm4(af[mf], aab + (m * SKA + ks + a_kof) * 2);
            }
            uint32_t bf[2][4];   // bf[nfp]: r0=(n0-7,klo) r1=(n0-7,khi) r2=(n8-15,klo) r3=(n8-15,khi)
#pragma unroll
            for (int nfp = 0; nfp < 2; nfp++) {
                int n = warp_n * 32 + nfp * 16 + b_row;
                ldsm4(bf[nfp], bbb + (n * SKB + ks + b_kof) * 2);
            }
#pragma unroll
            for (int mf = 0; mf < 4; mf++) {
#pragma unroll
                for (int nf = 0; nf < 4; nf++)
                    mma_f16(acc[mf][nf], af[mf], &bf[nf >> 1][(nf & 1) * 2]);
            }
        }
        __syncthreads();
    }

    // Epilogue: C frag lane (grp,2tig): c0,c1 rows grp; c2,c3 rows grp+8
#pragma unroll
    for (int mf = 0; mf < 4; mf++) {
        int m0 = bm + warp_m * 64 + mf * 16 + grp;
#pragma unroll
        for (int nf = 0; nf < 4; nf++) {
            int n0 = bn + warp_n * 32 + nf * 8 + 2 * tig;
            float b0 = bias[n0], b1 = bias[n0 + 1];
            if (m0 < NN) {
                float v0 = softplusf(acc[mf][nf][0] + b0);
                float v1 = softplusf(acc[mf][nf][1] + b1);
                *(__half2*)(out + (size_t)m0 * Fout + n0) = __floats2half2_rn(v0, v1);
            }
            if (m0 + 8 < NN) {
                float v0 = softplusf(acc[mf][nf][2] + b0);
                float v1 = softplusf(acc[mf][nf][3] + b1);
                *(__half2*)(out + (size_t)(m0 + 8) * Fout + n0) = __floats2half2_rn(v0, v1);
            }
        }
    }
}

// ---------------------------------------------------------------------------
// Small GEMM, BN == Fout exactly (16/32/64). Optional fp16 output.
template<int BN>
__global__ void gemm3_small_t(const float* __restrict__ A0, const float* __restrict__ A1,
                              const float* __restrict__ A2, const float* __restrict__ W,
                              const float* __restrict__ bias, float* __restrict__ out,
                              __half* __restrict__ outh, int Fin) {
    constexpr int BM = 64, BK = 8;
    constexpr int TN = BN / 16;
    __shared__ float sA[BK][BM];
    __shared__ float sB[BK][BN];
    const int bm = blockIdx.x * BM;
    const int tid = threadIdx.x;
    const int tx = tid & 15, ty = tid >> 4;

    float acc[4][TN];
#pragma unroll
    for (int i = 0; i < 4; i++)
#pragma unroll
        for (int j = 0; j < TN; j++) acc[i][j] = 0.f;

    const float* As[3] = {A0, A1, A2};
    for (int k = 0; k < 3; k++) {
        const float* A = As[k];
        const float* Wk = W + (size_t)k * Fin * BN;
        for (int i0 = 0; i0 < Fin; i0 += BK) {
#pragma unroll
            for (int l = 0; l < 2; l++) {
                int idx = tid + l * 256;
                int mm = idx >> 3, kk = idx & 7;
                int m = bm + mm;
                sA[kk][mm] = (m < NN) ? A[(size_t)m * Fin + i0 + kk] : 0.f;
            }
            for (int idx = tid; idx < BK * BN; idx += 256) {
                int kk = idx / BN, nn = idx - kk * BN;
                sB[kk][nn] = Wk[(size_t)(i0 + kk) * BN + nn];
            }
            __syncthreads();
#pragma unroll
            for (int kk = 0; kk < BK; kk++) {
                float a[4], b[TN];
#pragma unroll
                for (int i = 0; i < 4; i++) a[i] = sA[kk][ty * 4 + i];
#pragma unroll
                for (int j = 0; j < TN; j++) b[j] = sB[kk][tx * TN + j];
#pragma unroll
                for (int i = 0; i < 4; i++)
#pragma unroll
                    for (int j = 0; j < TN; j++) acc[i][j] = fmaf(a[i], b[j], acc[i][j]);
            }
            __syncthreads();
        }
    }

#pragma unroll
    for (int i = 0; i < 4; i++) {
        int m = bm + ty * 4 + i;
        if (m >= NN) continue;
#pragma unroll
        for (int j = 0; j < TN; j++) {
            int n = tx * TN + j;
            float v = softplusf(acc[i][j] + bias[n]);
            if (outh) outh[(size_t)m * BN + n] = __float2half_rn(v);
            else out[(size_t)m * BN + n] = v;
        }
    }
}

// final FC: out[n][0:3] = h[n][0:512] @ fc_w (512x3) + fc_b; one warp per node, fp16 h
__global__ void fc_kernel(const __half* __restrict__ h, const float* __restrict__ fw,
                          const float* __restrict__ fb, float* __restrict__ out) {
    int gw = (blockIdx.x * blockDim.x + threadIdx.x) >> 5;
    int lane = threadIdx.x & 31;
    if (gw >= NN) return;
    const __half* hr = h + (size_t)gw * 512;
    float a0 = 0.f, a1 = 0.f, a2 = 0.f;
    for (int i = lane; i < 512; i += 32) {
        float v = __half2float(hr[i]);
        a0 = fmaf(v, fw[i * 3 + 0], a0);
        a1 = fmaf(v, fw[i * 3 + 1], a1);
        a2 = fmaf(v, fw[i * 3 + 2], a2);
    }
#pragma unroll
    for (int o = 16; o > 0; o >>= 1) {
        a0 += __shfl_down_sync(0xffffffffu, a0, o);
        a1 += __shfl_down_sync(0xffffffffu, a1, o);
        a2 += __shfl_down_sync(0xffffffffu, a2, o);
    }
    if (lane == 0) {
        out[gw * 3 + 0] = a0 + fb[0];
        out[gw * 3 + 1] = a1 + fb[1];
        out[gw * 3 + 2] = a2 + fb[2];
    }
}

// ---------------------------------------------------------------------------

extern "C" void kernel_launch(void* const* d_in, const int* in_sizes, int n_in,
                              void* d_out, int out_size) {
    (void)in_sizes; (void)n_in; (void)out_size;

    const float* x   = (const float*)d_in[0];
    const int*   ei  = (const int*)d_in[1];
    const float* ew  = (const float*)d_in[2];
    const float* Wp[6];
    const float* bp[6];
    for (int l = 0; l < 6; l++) {
        Wp[l] = (const float*)d_in[4 + 2 * l];
        bp[l] = (const float*)d_in[5 + 2 * l];
    }
    const float* fcw = (const float*)d_in[16];
    const float* fcb = (const float*)d_in[17];
    float* out = (float*)d_out;

    float *bufA, *bufB, *t1f, *t2f, *deg;
    uint4 *hA, *hB, *t1h, *t2h, *wh;
    int *cnt;
    cudaGetSymbolAddress((void**)&bufA, g_bufA);
    cudaGetSymbolAddress((void**)&bufB, g_bufB);
    cudaGetSymbolAddress((void**)&t1f,  g_t1f);
    cudaGetSymbolAddress((void**)&t2f,  g_t2f);
    cudaGetSymbolAddress((void**)&hA,   g_hA);
    cudaGetSymbolAddress((void**)&hB,   g_hB);
    cudaGetSymbolAddress((void**)&t1h,  g_t1h);
    cudaGetSymbolAddress((void**)&t2h,  g_t2h);
    cudaGetSymbolAddress((void**)&wh,   g_wh);
    cudaGetSymbolAddress((void**)&deg,  g_deg);
    cudaGetSymbolAddress((void**)&cnt,  g_cnt);

    const int* row = ei;
    const int* col = ei + EE;

    // convert + transpose tc-layer weights to fp16 [n][k]
    const int woff[3] = {0, 24576, 122880};     // halves: 3*64*128, +3*128*256
    const int wlen[3] = {24576, 98304, 393216};
    for (int i = 0; i < 3; i++)
        convw_kernel<<<(wlen[i] + 255) / 256, 256>>>(
            Wp[3 + i], (__half*)wh + woff[i], DIMS[3 + i], DIMS[4 + i]);

    // CSC build
    cudaMemsetAsync(deg, 0, NN * sizeof(float));
    cudaMemsetAsync(cnt, 0, NN * sizeof(int));
    deg_count_kernel<<<(EE + 255) / 256, 256>>>(row, col, ew);
    scan_kernel<<<1, 1024>>>();
    fill_kernel<<<(EE + 255) / 256, 256>>>(row, col, ew);

    // ---- layers 0-2: fp32 SIMT ----
    {
        // layer 0: Fin=128, Fout=16
        int FV = 32, npb = 8;
        unsigned gb = (NN + npb - 1) / npb;
        spmm_gather<<<gb, 256>>>((const float4*)x, nullptr, 1.f, 0.f, (float4*)t1f, FV, npb);
        spmm_gather<<<gb, 256>>>((const float4*)t1f, (const float4*)x, 2.f, -1.f, (float4*)t2f, FV, npb);
        gemm3_small_t<16><<<(NN + 63) / 64, 256>>>(x, t1f, t2f, Wp[0], bp[0], bufA, nullptr, 128);

        // layer 1: Fin=16, Fout=32
        FV = 4; npb = 64; gb = (NN + npb - 1) / npb;
        spmm_gather<<<gb, 256>>>((const float4*)bufA, nullptr, 1.f, 0.f, (float4*)t1f, FV, npb);
        spmm_gather<<<gb, 256>>>((const float4*)t1f, (const float4*)bufA, 2.f, -1.f, (float4*)t2f, FV, npb);
        gemm3_small_t<32><<<(NN + 63) / 64, 256>>>(bufA, t1f, t2f, Wp[1], bp[1], bufB, nullptr, 16);

        // layer 2: Fin=32, Fout=64 -> fp16 output (hA)
        FV = 8; npb = 32; gb = (NN + npb - 1) / npb;
        spmm_gather<<<gb, 256>>>((const float4*)bufB, nullptr, 1.f, 0.f, (float4*)t1f, FV, npb);
        spmm_gather<<<gb, 256>>>((const float4*)t1f, (const float4*)bufB, 2.f, -1.f, (float4*)t2f, FV, npb);
        gemm3_small_t<64><<<(NN + 63) / 64, 256>>>(bufB, t1f, t2f, Wp[2], bp[2], nullptr, (__half*)hA, 32);
    }

    // ---- layers 3-5: fp16 tensor-core ----
    uint4* hin = hA;
    uint4* hout = hB;
    for (int l = 3; l < 6; l++) {
        int Fin = DIMS[l], Fout = DIMS[l + 1];
        int FV = Fin / 8;            // uint4 lanes of 8 halves
        int npb = 256 / FV;
        unsigned gb = (NN + npb - 1) / npb;

        spmm_gather_h<<<gb, 256>>>(hin, nullptr, 1.f, 0.f, t1h, FV, npb);
        spmm_gather_h<<<gb, 256>>>(t1h, hin, 2.f, -1.f, t2h, FV, npb);

        dim3 grid((NN + 127) / 128, Fout / 128);
        gemm3_tc_h<<<grid, 256>>>((const __half*)hin, (const __half*)t1h, (const __half*)t2h,
                                  (const __half*)wh + woff[l - 3], bp[l], (__half*)hout,
                                  Fin, Fout);
        uint4* tmp = hin; hin = hout; hout = tmp;
    }

    // final FC 512 -> 3 (hin holds h6 after the swap)
    fc_kernel<<<((long)NN * 32 + 255) / 256, 256>>>((const __half*)hin, fcw, fcb, out);
}

// round 13
// speedup vs baseline: 5.1255x; 1.0450x over previous
#include <cuda_runtime.h>
#include <cuda_fp16.h>
#include <math.h>
#include <stdint.h>

#define NN 30000
#define EE 480000

// dims per layer: input 128 -> 16 -> 32 -> 64 -> 128 -> 256 -> 512

// Scratch (static __device__ arrays; no allocations allowed)
__device__ uint4 g_x16[(size_t)NN * 16];        // x in fp16 (NN x 128)
__device__ uint4 g_hA[(size_t)NN * 64];         // fp16 ping-pong (up to NN x 512)
__device__ uint4 g_hB[(size_t)NN * 64];
__device__ uint4 g_t1h[(size_t)NN * 32];        // fp16 Tx (up to NN x 256)
__device__ uint4 g_t2h[(size_t)NN * 32];
__device__ uint4 g_wh[66240];                   // fp16 transposed weights, all 6 layers
__device__ float g_deg[NN];
__device__ int   g_cnt[NN];
__device__ int   g_ptr[NN + 1];
__device__ int   g_cur[NN];
__device__ int   g_srcidx[EE];
__device__ float g_wsort[EE];

// ---------------------------------------------------------------------------
__device__ __forceinline__ float softplusf(float x) {
    return fmaxf(x, 0.f) + log1pf(__expf(-fabsf(x)));
}

__device__ __forceinline__ uint32_t smem_u32(const void* p) {
    return (uint32_t)__cvta_generic_to_shared(p);
}

__device__ __forceinline__ void cp_async16(uint32_t dst, const void* src, int srcBytes) {
    asm volatile("cp.async.ca.shared.global [%0], [%1], 16, %2;\n"
                 :: "r"(dst), "l"(src), "r"(srcBytes));
}
__device__ __forceinline__ void cp_commit() {
    asm volatile("cp.async.commit_group;\n" ::: "memory");
}

__device__ __forceinline__ void ldsm4(uint32_t (&r)[4], uint32_t addr) {
    asm volatile("ldmatrix.sync.aligned.m8n8.x4.shared.b16 {%0,%1,%2,%3}, [%4];"
                 : "=r"(r[0]), "=r"(r[1]), "=r"(r[2]), "=r"(r[3]) : "r"(addr));
}

__device__ __forceinline__ void mma_f16(float (&d)[4], const uint32_t (&a)[4],
                                        const uint32_t* b) {
    asm volatile(
        "mma.sync.aligned.m16n8k16.row.col.f32.f16.f16.f32 "
        "{%0,%1,%2,%3},{%4,%5,%6,%7},{%8,%9},{%0,%1,%2,%3};"
        : "+f"(d[0]), "+f"(d[1]), "+f"(d[2]), "+f"(d[3])
        : "r"(a[0]), "r"(a[1]), "r"(a[2]), "r"(a[3]), "r"(b[0]), "r"(b[1]));
}

// ---------------------------------------------------------------------------
// CSC build
__global__ void deg_count_kernel(const int* __restrict__ row, const int* __restrict__ col,
                                 const float* __restrict__ ew) {
    int e = blockIdx.x * blockDim.x + threadIdx.x;
    if (e < EE) {
        atomicAdd(&g_deg[row[e]], ew[e]);
        atomicAdd(&g_cnt[col[e]], 1);
    }
}

__global__ void scan_kernel() {
    const int tid = threadIdx.x;
    const int lane = tid & 31, wid = tid >> 5;
    __shared__ int wsum[32];
    __shared__ int s_off;
    if (tid == 0) s_off = 0;
    __syncthreads();
    for (int base = 0; base < NN; base += 1024) {
        int i = base + tid;
        int v = (i < NN) ? g_cnt[i] : 0;
        int incl = v;
#pragma unroll
        for (int o = 1; o < 32; o <<= 1) {
            int t = __shfl_up_sync(0xffffffffu, incl, o);
            if (lane >= o) incl += t;
        }
        if (lane == 31) wsum[wid] = incl;
        __syncthreads();
        if (wid == 0) {
            int s = wsum[lane];
            int inc2 = s;
#pragma unroll
            for (int o = 1; o < 32; o <<= 1) {
                int t = __shfl_up_sync(0xffffffffu, inc2, o);
                if (lane >= o) inc2 += t;
            }
            wsum[lane] = inc2 - s;
        }
        __syncthreads();
        int excl = s_off + wsum[wid] + incl - v;
        if (i < NN) { g_ptr[i] = excl; g_cur[i] = excl; }
        __syncthreads();
        if (tid == 1023) s_off += wsum[31] + incl;
        __syncthreads();
    }
    if (tid == 0) g_ptr[NN] = s_off;
}

__global__ void fill_kernel(const int* __restrict__ row, const int* __restrict__ col,
                            const float* __restrict__ ew) {
    int e = blockIdx.x * blockDim.x + threadIdx.x;
    if (e < EE) {
        int c = col[e];
        int p = atomicAdd(&g_cur[c], 1);
        int r = row[e];
        g_srcidx[p] = r;
        float d = g_deg[r];
        g_wsort[p] = (d > 0.f) ? (-ew[e] / d) : 0.f;
    }
}

// one-shot: x fp32 -> fp16
__global__ void convx_kernel(const float4* __restrict__ src, __half2* __restrict__ dst, int n4) {
    int i = blockIdx.x * blockDim.x + threadIdx.x;
    if (i < n4) {
        float4 v = src[i];
        dst[2 * i + 0] = __floats2half2_rn(v.x, v.y);
        dst[2 * i + 1] = __floats2half2_rn(v.z, v.w);
    }
}

// one-shot: all 6 W tensors (3,Fin,Fout) fp32 -> (3,Fout,Fin) fp16 transposed
#define WTOT 529920
__global__ void convw_all(const float* W0, const float* W1, const float* W2,
                          const float* W3, const float* W4, const float* W5,
                          __half* __restrict__ dst) {
    int idx = blockIdx.x * blockDim.x + threadIdx.x;
    if (idx >= WTOT) return;
    const int offs[7]  = {0, 6144, 7680, 13824, 38400, 136704, WTOT};
    const int fins[6]  = {128, 16, 32, 64, 128, 256};
    const int fouts[6] = {16, 32, 64, 128, 256, 512};
    const float* Ws[6] = {W0, W1, W2, W3, W4, W5};
    int l = 0;
    while (idx >= offs[l + 1]) l++;
    int rem = idx - offs[l];
    int Fin = fins[l], Fout = fouts[l];
    int s = rem / (Fin * Fout);
    int r2 = rem - s * Fin * Fout;
    int k = r2 / Fout, n = r2 - k * Fout;
    dst[(size_t)offs[l] + (size_t)s * Fin * Fout + (size_t)n * Fin + k] =
        __float2half_rn(Ws[l][rem]);
}

// ---------------------------------------------------------------------------
// fp16 gather SpMM. FV = Fin/8 (uint4 = 8 halves). fp32 accumulate.
// dst[c] = half( scale * sum w[e]*src[srcidx[e]] + addscale*addsrc[c] )
__global__ void spmm_gather_h(const uint4* __restrict__ src, const uint4* __restrict__ addsrc,
                              float scale, float addscale, uint4* __restrict__ dst,
                              int FV, int npb) {
    int ty = threadIdx.x / FV;
    int tx = threadIdx.x - ty * FV;
    int c = blockIdx.x * npb + ty;
    if (c >= NN) return;
    int beg = g_ptr[c], end = g_ptr[c + 1];
    float2 acc[4];
#pragma unroll
    for (int q = 0; q < 4; q++) acc[q] = make_float2(0.f, 0.f);

    if (FV >= 8) {
        // sub-warp group of FV lanes works one node: batch-load FV edges, shuffle-broadcast
        int wlane = threadIdx.x & 31;
        int gbase = wlane & ~(FV - 1);
        unsigned gmask = (FV == 32) ? 0xffffffffu : (((1u << FV) - 1u) << gbase);
        for (int eb = beg; eb < end; eb += FV) {
            int n = end - eb; if (n > FV) n = FV;
            int r_l = 0; float w_l = 0.f;
            if (tx < n) { r_l = g_srcidx[eb + tx]; w_l = g_wsort[eb + tx]; }
            for (int j = 0; j < n; j++) {
                int r = __shfl_sync(gmask, r_l, gbase + j);
                float w = __shfl_sync(gmask, w_l, gbase + j);
                uint4 v = src[(size_t)r * FV + tx];
                const __half2* hp = (const __half2*)&v;
#pragma unroll
                for (int q = 0; q < 4; q++) {
                    float2 f = __half22float2(hp[q]);
                    acc[q].x = fmaf(w, f.x, acc[q].x);
                    acc[q].y = fmaf(w, f.y, acc[q].y);
                }
            }
        }
    } else {
        for (int e = beg; e < end; e++) {
            int r = g_srcidx[e];
            float w = g_wsort[e];
            uint4 v = src[(size_t)r * FV + tx];
            const __half2* hp = (const __half2*)&v;
#pragma unroll
            for (int q = 0; q < 4; q++) {
                float2 f = __half22float2(hp[q]);
                acc[q].x = fmaf(w, f.x, acc[q].x);
                acc[q].y = fmaf(w, f.y, acc[q].y);
            }
        }
    }

    uint4 r;
    __half2* rp = (__half2*)&r;
    if (addsrc) {
        uint4 a = addsrc[(size_t)c * FV + tx];
        const __half2* ap = (const __half2*)&a;
#pragma unroll
        for (int q = 0; q < 4; q++) {
            float2 af = __half22float2(ap[q]);
            rp[q] = __floats2half2_rn(fmaf(addscale, af.x, scale * acc[q].x),
                                      fmaf(addscale, af.y, scale * acc[q].y));
        }
    } else {
#pragma unroll
        for (int q = 0; q < 4; q++)
            rp[q] = __floats2half2_rn(scale * acc[q].x, scale * acc[q].y);
    }
    dst[(size_t)c * FV + tx] = r;
}

// ---------------------------------------------------------------------------
// Wide fp16 tc GEMM (Fout % 128 == 0): 128x128x32 tiles, 3-stage cp.async,
// dynamic smem (61440 B). Wt is (3,Fout,Fin) fp16.
__global__ __launch_bounds__(256) void gemm3_tc_h(
        const __half* __restrict__ A0, const __half* __restrict__ A1,
        const __half* __restrict__ A2, const __half* __restrict__ Wt,
        const float* __restrict__ bias, __half* __restrict__ out,
        int Fin, int Fout) {
    constexpr int BK = 32;
    constexpr int SK = 40;             // halves; conflict-free for ldmatrix
    constexpr int ASZ = 128 * SK;      // halves per operand per stage
    constexpr int STG = ASZ * 2;       // halves per stage (A+B)
    extern __shared__ __half smem_dyn[];

    const int tid = threadIdx.x;
    const int lane = tid & 31;
    const int warp = tid >> 5;
    const int warp_m = warp & 1;
    const int warp_n = warp >> 1;
    const int bm = blockIdx.x * 128, bn = blockIdx.y * 128;
    const int grp = lane >> 2;
    const int tig = lane & 3;

    const uint32_t s_base = smem_u32(smem_dyn);

    const int a_row = (lane & 7) + ((lane >> 3) & 1) * 8;
    const int a_kof = ((lane >> 4) & 1) * 8;
    const int b_row = (lane & 7) + ((lane >> 4) & 1) * 8;
    const int b_kof = ((lane >> 3) & 1) * 8;

    float acc[4][4][4];
#pragma unroll
    for (int i = 0; i < 4; i++)
#pragma unroll
        for (int j = 0; j < 4; j++)
#pragma unroll
            for (int v = 0; v < 4; v++) acc[i][j][v] = 0.f;

    const __half* As[3] = {A0, A1, A2};
    const int KT = 3 * Fin;
    const int T = KT / BK;

    auto load_tile = [&](int t, int st) {
        int k0 = t * BK;
        int seg = k0 / Fin;
        int koff = k0 - seg * Fin;
        const __half* Ap = As[seg];
        const __half* Bp = Wt + (size_t)seg * Fin * Fout;
        uint32_t da = s_base + (st * STG) * 2;
        uint32_t db = da + ASZ * 2;
#pragma unroll
        for (int i = 0; i < 2; i++) {
            int chunk = tid + i * 256;
            int r = chunk >> 2;              // 0..127
            int kc = (chunk & 3) * 8;
            int gm = bm + r;
            cp_async16(da + (r * SK + kc) * 2, Ap + (size_t)gm * Fin + koff + kc,
                       gm < NN ? 16 : 0);
            int gn = bn + r;
            cp_async16(db + (r * SK + kc) * 2, Bp + (size_t)gn * Fin + koff + kc, 16);
        }
        cp_commit();
    };

    load_tile(0, 0);
    load_tile(1, 1);

    for (int t = 0; t < T; t++) {
        int st = t % 3;
        if (t + 2 < T) {
            load_tile(t + 2, (t + 2) % 3);
            asm volatile("cp.async.wait_group 2;\n" ::: "memory");
        } else if (t + 1 < T) {
            asm volatile("cp.async.wait_group 1;\n" ::: "memory");
        } else {
            asm volatile("cp.async.wait_group 0;\n" ::: "memory");
        }
        __syncthreads();

        uint32_t aab = s_base + (st * STG) * 2;
        uint32_t bbb = aab + ASZ * 2;
#pragma unroll
        for (int ks = 0; ks < BK; ks += 16) {
            uint32_t af[4][4];
#pragma unroll
            for (int mf = 0; mf < 4; mf++) {
                int m = warp_m * 64 + mf * 16 + a_row;
                ldsm4(af[mf], aab + (m * SK + ks + a_kof) * 2);
            }
            uint32_t bf[2][4];
#pragma unroll
            for (int nfp = 0; nfp < 2; nfp++) {
                int n = warp_n * 32 + nfp * 16 + b_row;
                ldsm4(bf[nfp], bbb + (n * SK + ks + b_kof) * 2);
            }
#pragma unroll
            for (int mf = 0; mf < 4; mf++)
#pragma unroll
                for (int nf = 0; nf < 4; nf++)
                    mma_f16(acc[mf][nf], af[mf], &bf[nf >> 1][(nf & 1) * 2]);
        }
        __syncthreads();
    }

#pragma unroll
    for (int mf = 0; mf < 4; mf++) {
        int m0 = bm + warp_m * 64 + mf * 16 + grp;
#pragma unroll
        for (int nf = 0; nf < 4; nf++) {
            int n0 = bn + warp_n * 32 + nf * 8 + 2 * tig;
            float b0 = bias[n0], b1 = bias[n0 + 1];
            if (m0 < NN) {
                float v0 = softplusf(acc[mf][nf][0] + b0);
                float v1 = softplusf(acc[mf][nf][1] + b1);
                *(__half2*)(out + (size_t)m0 * Fout + n0) = __floats2half2_rn(v0, v1);
            }
            if (m0 + 8 < NN) {
                float v0 = softplusf(acc[mf][nf][2] + b0);
                float v1 = softplusf(acc[mf][nf][3] + b1);
                *(__half2*)(out + (size_t)(m0 + 8) * Fout + n0) = __floats2half2_rn(v0, v1);
            }
        }
    }
}

// ---------------------------------------------------------------------------
// Narrow fp16 tc GEMM (Fout = 16/32/64): BM=128 (16 rows/warp), BK=16,
// B fully smem-resident, A streamed through 3-stage cp.async ring.
template<int BN, int FIN>
__global__ __launch_bounds__(256) void gemm3_tc_n(
        const __half* __restrict__ A0, const __half* __restrict__ A1,
        const __half* __restrict__ A2, const __half* __restrict__ Wt,
        const float* __restrict__ bias, __half* __restrict__ out) {
    constexpr int KT = 3 * FIN;
    constexpr int BK = 16;
    constexpr int T = KT / BK;
    constexpr int SKA = 24;            // halves; 12 words % 32 -> CF ldmatrix
    constexpr int SKB = KT + 8;        // halves; checked CF for KT in {48,96,384}
    constexpr int ASZ = 128 * SKA;
    constexpr int NF = BN / 8;
    __shared__ __align__(16) __half sA[3][ASZ];
    __shared__ __align__(16) __half sB[BN * SKB];

    const int tid = threadIdx.x;
    const int lane = tid & 31;
    const int warp = tid >> 5;         // rows [warp*16, warp*16+16)
    const int bm = blockIdx.x * 128;
    const int grp = lane >> 2;
    const int tig = lane & 3;

    const uint32_t sA_base = smem_u32(&sA[0][0]);
    const uint32_t sB_base = smem_u32(&sB[0]);

    const int a_row = (lane & 7) + ((lane >> 3) & 1) * 8;
    const int a_kof = ((lane >> 4) & 1) * 8;
    const int b_row = (lane & 7) + ((lane >> 4) & 1) * 8;
    const int b_kof = ((lane >> 3) & 1) * 8;

    float acc[NF][4];
#pragma unroll
    for (int i = 0; i < NF; i++)
#pragma unroll
        for (int v = 0; v < 4; v++) acc[i][v] = 0.f;

    const __half* As[3] = {A0, A1, A2};

    // B: whole (KT x BN) resident, loaded once (group with A tile 0)
    constexpr int KC = KT / 8;
    for (int idx = tid; idx < BN * KC; idx += 256) {
        int n = idx / KC, c = idx - n * KC;
        int kt = c * 8;
        int s = kt / FIN, k = kt - s * FIN;
        cp_async16(sB_base + (n * SKB + kt) * 2,
                   Wt + (size_t)s * FIN * BN + (size_t)n * FIN + k, 16);
    }

    auto load_tileA = [&](int t, int st) {
        int k0 = t * BK;
        int s = k0 / FIN, koff = k0 - s * FIN;
        const __half* Ap = As[s];
        int r = tid >> 1, kc = (tid & 1) * 8;
        int gm = bm + r;
        cp_async16(sA_base + (st * ASZ + r * SKA + kc) * 2,
                   Ap + (size_t)gm * FIN + koff + kc, gm < NN ? 16 : 0);
    };

    load_tileA(0, 0);
    cp_commit();                       // group: B + A0
    if (T > 1) { load_tileA(1, 1); cp_commit(); }

    for (int t = 0; t < T; t++) {
        int st = t % 3;
        if (t + 2 < T) {
            load_tileA(t + 2, (t + 2) % 3);
            cp_commit();
            asm volatile("cp.async.wait_group 2;\n" ::: "memory");
        } else if (t + 1 < T) {
            asm volatile("cp.async.wait_group 1;\n" ::: "memory");
        } else {
            asm volatile("cp.async.wait_group 0;\n" ::: "memory");
        }
        __syncthreads();

        uint32_t af[4];
        ldsm4(af, sA_base + (st * ASZ + (warp * 16 + a_row) * SKA + a_kof) * 2);
        uint32_t bf[(NF + 1) / 2][4];
#pragma unroll
        for (int nfp = 0; nfp < (NF + 1) / 2; nfp++)
            ldsm4(bf[nfp], sB_base + ((nfp * 16 + b_row) * SKB + t * BK + b_kof) * 2);
#pragma unroll
        for (int nf = 0; nf < NF; nf++)
            mma_f16(acc[nf], af, &bf[nf >> 1][(nf & 1) * 2]);
        __syncthreads();
    }

    int m0 = bm + warp * 16 + grp;
#pragma unroll
    for (int nf = 0; nf < NF; nf++) {
        int n0 = nf * 8 + 2 * tig;
        float b0 = bias[n0], b1 = bias[n0 + 1];
        if (m0 < NN) {
            float v0 = softplusf(acc[nf][0] + b0);
            float v1 = softplusf(acc[nf][1] + b1);
            *(__half2*)(out + (size_t)m0 * BN + n0) = __floats2half2_rn(v0, v1);
        }
        if (m0 + 8 < NN) {
            float v0 = softplusf(acc[nf][2] + b0);
            float v1 = softplusf(acc[nf][3] + b1);
            *(__half2*)(out + (size_t)(m0 + 8) * BN + n0) = __floats2half2_rn(v0, v1);
        }
    }
}

// final FC: out[n][0:3] = h[n][0:512] @ fc_w (512x3) + fc_b; one warp per node, fp16 h
__global__ void fc_kernel(const __half* __restrict__ h, const float* __restrict__ fw,
                          const float* __restrict__ fb, float* __restrict__ out) {
    int gw = (blockIdx.x * blockDim.x + threadIdx.x) >> 5;
    int lane = threadIdx.x & 31;
    if (gw >= NN) return;
    const __half* hr = h + (size_t)gw * 512;
    float a0 = 0.f, a1 = 0.f, a2 = 0.f;
    for (int i = lane; i < 512; i += 32) {
        float v = __half2float(hr[i]);
        a0 = fmaf(v, fw[i * 3 + 0], a0);
        a1 = fmaf(v, fw[i * 3 + 1], a1);
        a2 = fmaf(v, fw[i * 3 + 2], a2);
    }
#pragma unroll
    for (int o = 16; o > 0; o >>= 1) {
        a0 += __shfl_down_sync(0xffffffffu, a0, o);
        a1 += __shfl_down_sync(0xffffffffu, a1, o);
        a2 += __shfl_down_sync(0xffffffffu, a2, o);
    }
    if (lane == 0) {
        out[gw * 3 + 0] = a0 + fb[0];
        out[gw * 3 + 1] = a1 + fb[1];
        out[gw * 3 + 2] = a2 + fb[2];
    }
}

// ---------------------------------------------------------------------------

extern "C" void kernel_launch(void* const* d_in, const int* in_sizes, int n_in,
                              void* d_out, int out_size) {
    (void)in_sizes; (void)n_in; (void)out_size;

    const float* x   = (const float*)d_in[0];
    const int*   ei  = (const int*)d_in[1];
    const float* ew  = (const float*)d_in[2];
    const float* Wp[6];
    const float* bp[6];
    for (int l = 0; l < 6; l++) {
        Wp[l] = (const float*)d_in[4 + 2 * l];
        bp[l] = (const float*)d_in[5 + 2 * l];
    }
    const float* fcw = (const float*)d_in[16];
    const float* fcb = (const float*)d_in[17];
    float* out = (float*)d_out;

    uint4 *x16, *hA, *hB, *t1h, *t2h, *wh;
    float *deg;
    int *cnt;
    cudaGetSymbolAddress((void**)&x16, g_x16);
    cudaGetSymbolAddress((void**)&hA,  g_hA);
    cudaGetSymbolAddress((void**)&hB,  g_hB);
    cudaGetSymbolAddress((void**)&t1h, g_t1h);
    cudaGetSymbolAddress((void**)&t2h, g_t2h);
    cudaGetSymbolAddress((void**)&wh,  g_wh);
    cudaGetSymbolAddress((void**)&deg, g_deg);
    cudaGetSymbolAddress((void**)&cnt, g_cnt);

    const int* row = ei;
    const int* col = ei + EE;

    // wide kernel needs 60KB dynamic smem
    cudaFuncSetAttribute(gemm3_tc_h, cudaFuncAttributeMaxDynamicSharedMemorySize, 61440);

    // one-shot conversions
    convx_kernel<<<(NN * 32 + 255) / 256, 256>>>((const float4*)x, (__half2*)x16, NN * 32);
    convw_all<<<(WTOT + 255) / 256, 256>>>(Wp[0], Wp[1], Wp[2], Wp[3], Wp[4], Wp[5],
                                           (__half*)wh);

    // CSC build
    cudaMemsetAsync(deg, 0, NN * sizeof(float));
    cudaMemsetAsync(cnt, 0, NN * sizeof(int));
    deg_count_kernel<<<(EE + 255) / 256, 256>>>(row, col, ew);
    scan_kernel<<<1, 1024>>>();
    fill_kernel<<<(EE + 255) / 256, 256>>>(row, col, ew);

    const __half* wh_h = (const __half*)wh;
    const int woff[6] = {0, 6144, 7680, 13824, 38400, 136704};
    const int FINs[7] = {128, 16, 32, 64, 128, 256, 512};

    uint4* hin = x16;
    uint4* hout = hA;
    for (int l = 0; l < 6; l++) {
        int Fin = FINs[l], Fout = FINs[l + 1];
        int FV = Fin / 8;
        int npb = 256 / FV;
        unsigned gb = (NN + npb - 1) / npb;

        spmm_gather_h<<<gb, 256>>>(hin, nullptr, 1.f, 0.f, t1h, FV, npb);
        spmm_gather_h<<<gb, 256>>>(t1h, hin, 2.f, -1.f, t2h, FV, npb);

        const __half* A0 = (const __half*)hin;
        const __half* A1 = (const __half*)t1h;
        const __half* A2 = (const __half*)t2h;
        __half* O = (__half*)hout;
        unsigned gx = (NN + 127) / 128;
        if (Fout == 16)
            gemm3_tc_n<16, 128><<<gx, 256>>>(A0, A1, A2, wh_h + woff[l], bp[l], O);
        else if (Fout == 32)
            gemm3_tc_n<32, 16><<<gx, 256>>>(A0, A1, A2, wh_h + woff[l], bp[l], O);
        else if (Fout == 64)
            gemm3_tc_n<64, 32><<<gx, 256>>>(A0, A1, A2, wh_h + woff[l], bp[l], O);
        else {
            dim3 grid(gx, Fout / 128);
            gemm3_tc_h<<<grid, 256, 61440>>>(A0, A1, A2, wh_h + woff[l], bp[l], O,
                                             Fin, Fout);
        }

        // ping-pong (x16 only ever an input)
        hin = hout;
        hout = (hin == hA) ? hB : hA;
    }

    // final FC 512 -> 3
    fc_kernel<<<((long)NN * 32 + 255) / 256, 256>>>((const __half*)hin, fcw, fcb, out);
}

// round 14
// speedup vs baseline: 5.3062x; 1.0353x over previous
#include <cuda_runtime.h>
#include <cuda_fp16.h>
#include <math.h>
#include <stdint.h>

#define NN 30000
#define EE 480000
#define SCB 1024
#define NCHUNK ((NN + SCB - 1) / SCB)   // 30

// dims per layer: input 128 -> 16 -> 32 -> 64 -> 128 -> 256 -> 512

// Scratch (static __device__ arrays; no allocations allowed)
__device__ uint4  g_x16[(size_t)NN * 16];        // x in fp16 (NN x 128)
__device__ uint4  g_hA[(size_t)NN * 64];         // fp16 ping-pong (up to NN x 512)
__device__ uint4  g_hB[(size_t)NN * 64];
__device__ uint4  g_t1h[(size_t)NN * 32];        // fp16 Tx (up to NN x 256)
__device__ uint4  g_t2h[(size_t)NN * 32];
__device__ uint4  g_wh[66240];                   // fp16 transposed weights, all 6 layers
__device__ float  g_deg[NN];
__device__ int    g_cnt[NN];
__device__ int    g_ptr[NN + 1];
__device__ int    g_cur[NN];
__device__ float2 g_edge[EE];                    // packed (srcidx-bits, weight) per CSC slot
__device__ int    g_bsum[32];
__device__ int    g_boff[32];

// ---------------------------------------------------------------------------
__device__ __forceinline__ float softplusf(float x) {
    return fmaxf(x, 0.f) + log1pf(__expf(-fabsf(x)));
}

__device__ __forceinline__ uint32_t smem_u32(const void* p) {
    return (uint32_t)__cvta_generic_to_shared(p);
}

__device__ __forceinline__ void cp_async16(uint32_t dst, const void* src, int srcBytes) {
    asm volatile("cp.async.ca.shared.global [%0], [%1], 16, %2;\n"
                 :: "r"(dst), "l"(src), "r"(srcBytes));
}
__device__ __forceinline__ void cp_commit() {
    asm volatile("cp.async.commit_group;\n" ::: "memory");
}

__device__ __forceinline__ void ldsm4(uint32_t (&r)[4], uint32_t addr) {
    asm volatile("ldmatrix.sync.aligned.m8n8.x4.shared.b16 {%0,%1,%2,%3}, [%4];"
                 : "=r"(r[0]), "=r"(r[1]), "=r"(r[2]), "=r"(r[3]) : "r"(addr));
}

__device__ __forceinline__ void mma_f16(float (&d)[4], const uint32_t (&a)[4],
                                        const uint32_t* b) {
    asm volatile(
        "mma.sync.aligned.m16n8k16.row.col.f32.f16.f16.f32 "
        "{%0,%1,%2,%3},{%4,%5,%6,%7},{%8,%9},{%0,%1,%2,%3};"
        : "+f"(d[0]), "+f"(d[1]), "+f"(d[2]), "+f"(d[3])
        : "r"(a[0]), "r"(a[1]), "r"(a[2]), "r"(a[3]), "r"(b[0]), "r"(b[1]));
}

// ---------------------------------------------------------------------------
// CSC build
__global__ void deg_count_kernel(const int* __restrict__ row, const int* __restrict__ col,
                                 const float* __restrict__ ew) {
    int e = blockIdx.x * blockDim.x + threadIdx.x;
    if (e < EE) {
        atomicAdd(&g_deg[row[e]], ew[e]);
        atomicAdd(&g_cnt[col[e]], 1);
    }
}

// multi-block scan, pass 1: chunk-local exclusive scan + chunk sums
__global__ void scan1_kernel() {
    const int b = blockIdx.x, tid = threadIdx.x;
    const int lane = tid & 31, wid = tid >> 5;
    __shared__ int wsum[32];
    int i = b * SCB + tid;
    int v = (i < NN) ? g_cnt[i] : 0;
    int incl = v;
#pragma unroll
    for (int o = 1; o < 32; o <<= 1) {
        int t = __shfl_up_sync(0xffffffffu, incl, o);
        if (lane >= o) incl += t;
    }
    if (lane == 31) wsum[wid] = incl;
    __syncthreads();
    if (wid == 0) {
        int s = wsum[lane];
        int inc2 = s;
#pragma unroll
        for (int o = 1; o < 32; o <<= 1) {
            int t = __shfl_up_sync(0xffffffffu, inc2, o);
            if (lane >= o) inc2 += t;
        }
        wsum[lane] = inc2 - s;   // exclusive warp prefix within chunk
    }
    __syncthreads();
    int excl = wsum[wid] + incl - v;   // chunk-local exclusive
    if (i < NN) g_ptr[i] = excl;
    if (tid == SCB - 1) g_bsum[b] = excl + v;
}

// pass 2: exclusive scan of 30 chunk sums (one warp)
__global__ void scan2_kernel() {
    int lane = threadIdx.x;
    int v = (lane < NCHUNK) ? g_bsum[lane] : 0;
    int incl = v;
#pragma unroll
    for (int o = 1; o < 32; o <<= 1) {
        int t = __shfl_up_sync(0xffffffffu, incl, o);
        if (lane >= o) incl += t;
    }
    if (lane < NCHUNK) g_boff[lane] = incl - v;
    if (lane == 31) g_ptr[NN] = incl;   // grand total
}

// pass 3: add chunk offsets
__global__ void scan3_kernel() {
    int b = blockIdx.x;
    int i = b * SCB + threadIdx.x;
    if (i < NN) {
        int p = g_ptr[i] + g_boff[b];
        g_ptr[i] = p;
        g_cur[i] = p;
    }
}

__global__ void fill_kernel(const int* __restrict__ row, const int* __restrict__ col,
                            const float* __restrict__ ew) {
    int e = blockIdx.x * blockDim.x + threadIdx.x;
    if (e < EE) {
        int c = col[e];
        int p = atomicAdd(&g_cur[c], 1);
        int r = row[e];
        float d = g_deg[r];
        float w = (d > 0.f) ? (-ew[e] / d) : 0.f;
        g_edge[p] = make_float2(__int_as_float(r), w);
    }
}

// one-shot merged conversion: x fp32->fp16, and all 6 W tensors -> (3,Fout,Fin) fp16 transposed
#define XV4 (NN * 32)       // 960000 float4 granules of x
#define WTOT 529920
__global__ void conv_all(const float4* __restrict__ x, __half2* __restrict__ x16,
                         const float* W0, const float* W1, const float* W2,
                         const float* W3, const float* W4, const float* W5,
                         __half* __restrict__ dst) {
    int idx = blockIdx.x * blockDim.x + threadIdx.x;
    if (idx < XV4) {
        float4 v = x[idx];
        x16[2 * idx + 0] = __floats2half2_rn(v.x, v.y);
        x16[2 * idx + 1] = __floats2half2_rn(v.z, v.w);
        return;
    }
    idx -= XV4;
    if (idx >= WTOT) return;
    const int offs[7]  = {0, 6144, 7680, 13824, 38400, 136704, WTOT};
    const int fins[6]  = {128, 16, 32, 64, 128, 256};
    const int fouts[6] = {16, 32, 64, 128, 256, 512};
    const float* Ws[6] = {W0, W1, W2, W3, W4, W5};
    int l = 0;
    while (idx >= offs[l + 1]) l++;
    int rem = idx - offs[l];
    int Fin = fins[l], Fout = fouts[l];
    int s = rem / (Fin * Fout);
    int r2 = rem - s * Fin * Fout;
    int k = r2 / Fout, n = r2 - k * Fout;
    dst[(size_t)offs[l] + (size_t)s * Fin * Fout + (size_t)n * Fin + k] =
        __float2half_rn(Ws[l][rem]);
}

// ---------------------------------------------------------------------------
// fp16 gather SpMM. FV = Fin/8 (uint4 = 8 halves). fp32 accumulate.
// dst[c] = half( scale * sum w[e]*src[srcidx[e]] + addscale*addsrc[c] )
__global__ void spmm_gather_h(const uint4* __restrict__ src, const uint4* __restrict__ addsrc,
                              float scale, float addscale, uint4* __restrict__ dst,
                              int FV, int npb) {
    int ty = threadIdx.x / FV;
    int tx = threadIdx.x - ty * FV;
    int c = blockIdx.x * npb + ty;
    if (c >= NN) return;
    int beg = g_ptr[c], end = g_ptr[c + 1];
    float2 acc[4];
#pragma unroll
    for (int q = 0; q < 4; q++) acc[q] = make_float2(0.f, 0.f);

    if (FV >= 8) {
        // sub-warp group of FV lanes works one node: batch-load FV edges, shuffle-broadcast
        int wlane = threadIdx.x & 31;
        int gbase = wlane & ~(FV - 1);
        unsigned gmask = (FV == 32) ? 0xffffffffu : (((1u << FV) - 1u) << gbase);
        for (int eb = beg; eb < end; eb += FV) {
            int n = end - eb; if (n > FV) n = FV;
            int r_l = 0; float w_l = 0.f;
            if (tx < n) {
                float2 e = g_edge[eb + tx];
                r_l = __float_as_int(e.x);
                w_l = e.y;
            }
            for (int j = 0; j < n; j++) {
                int r = __shfl_sync(gmask, r_l, gbase + j);
                float w = __shfl_sync(gmask, w_l, gbase + j);
                uint4 v = src[(size_t)r * FV + tx];
                const __half2* hp = (const __half2*)&v;
#pragma unroll
                for (int q = 0; q < 4; q++) {
                    float2 f = __half22float2(hp[q]);
                    acc[q].x = fmaf(w, f.x, acc[q].x);
                    acc[q].y = fmaf(w, f.y, acc[q].y);
                }
            }
        }
    } else {
        for (int e = beg; e < end; e++) {
            float2 ed = g_edge[e];
            int r = __float_as_int(ed.x);
            float w = ed.y;
            uint4 v = src[(size_t)r * FV + tx];
            const __half2* hp = (const __half2*)&v;
#pragma unroll
            for (int q = 0; q < 4; q++) {
                float2 f = __half22float2(hp[q]);
                acc[q].x = fmaf(w, f.x, acc[q].x);
                acc[q].y = fmaf(w, f.y, acc[q].y);
            }
        }
    }

    uint4 r;
    __half2* rp = (__half2*)&r;
    if (addsrc) {
        uint4 a = addsrc[(size_t)c * FV + tx];
        const __half2* ap = (const __half2*)&a;
#pragma unroll
        for (int q = 0; q < 4; q++) {
            float2 af = __half22float2(ap[q]);
            rp[q] = __floats2half2_rn(fmaf(addscale, af.x, scale * acc[q].x),
                                      fmaf(addscale, af.y, scale * acc[q].y));
        }
    } else {
#pragma unroll
        for (int q = 0; q < 4; q++)
            rp[q] = __floats2half2_rn(scale * acc[q].x, scale * acc[q].y);
    }
    dst[(size_t)c * FV + tx] = r;
}

// ---------------------------------------------------------------------------
// Wide fp16 tc GEMM (Fout % 128 == 0): 128x128x32 tiles, 3-stage cp.async,
// dynamic smem (61440 B). Wt is (3,Fout,Fin) fp16.
__global__ __launch_bounds__(256) void gemm3_tc_h(
        const __half* __restrict__ A0, const __half* __restrict__ A1,
        const __half* __restrict__ A2, const __half* __restrict__ Wt,
        const float* __restrict__ bias, __half* __restrict__ out,
        int Fin, int Fout) {
    constexpr int BK = 32;
    constexpr int SK = 40;             // halves; conflict-free for ldmatrix
    constexpr int ASZ = 128 * SK;      // halves per operand per stage
    constexpr int STG = ASZ * 2;       // halves per stage (A+B)
    extern __shared__ __half smem_dyn[];

    const int tid = threadIdx.x;
    const int lane = tid & 31;
    const int warp = tid >> 5;
    const int warp_m = warp & 1;
    const int warp_n = warp >> 1;
    const int bm = blockIdx.x * 128, bn = blockIdx.y * 128;
    const int grp = lane >> 2;
    const int tig = lane & 3;

    const uint32_t s_base = smem_u32(smem_dyn);

    const int a_row = (lane & 7) + ((lane >> 3) & 1) * 8;
    const int a_kof = ((lane >> 4) & 1) * 8;
    const int b_row = (lane & 7) + ((lane >> 4) & 1) * 8;
    const int b_kof = ((lane >> 3) & 1) * 8;

    float acc[4][4][4];
#pragma unroll
    for (int i = 0; i < 4; i++)
#pragma unroll
        for (int j = 0; j < 4; j++)
#pragma unroll
            for (int v = 0; v < 4; v++) acc[i][j][v] = 0.f;

    const __half* As[3] = {A0, A1, A2};
    const int KT = 3 * Fin;
    const int T = KT / BK;

    auto load_tile = [&](int t, int st) {
        int k0 = t * BK;
        int seg = k0 / Fin;
        int koff = k0 - seg * Fin;
        const __half* Ap = As[seg];
        const __half* Bp = Wt + (size_t)seg * Fin * Fout;
        uint32_t da = s_base + (st * STG) * 2;
        uint32_t db = da + ASZ * 2;
#pragma unroll
        for (int i = 0; i < 2; i++) {
            int chunk = tid + i * 256;
            int r = chunk >> 2;              // 0..127
            int kc = (chunk & 3) * 8;
            int gm = bm + r;
            cp_async16(da + (r * SK + kc) * 2, Ap + (size_t)gm * Fin + koff + kc,
                       gm < NN ? 16 : 0);
            int gn = bn + r;
            cp_async16(db + (r * SK + kc) * 2, Bp + (size_t)gn * Fin + koff + kc, 16);
        }
        cp_commit();
    };

    load_tile(0, 0);
    load_tile(1, 1);

    for (int t = 0; t < T; t++) {
        int st = t % 3;
        if (t + 2 < T) {
            load_tile(t + 2, (t + 2) % 3);
            asm volatile("cp.async.wait_group 2;\n" ::: "memory");
        } else if (t + 1 < T) {
            asm volatile("cp.async.wait_group 1;\n" ::: "memory");
        } else {
            asm volatile("cp.async.wait_group 0;\n" ::: "memory");
        }
        __syncthreads();

        uint32_t aab = s_base + (st * STG) * 2;
        uint32_t bbb = aab + ASZ * 2;
#pragma unroll
        for (int ks = 0; ks < BK; ks += 16) {
            uint32_t af[4][4];
#pragma unroll
            for (int mf = 0; mf < 4; mf++) {
                int m = warp_m * 64 + mf * 16 + a_row;
                ldsm4(af[mf], aab + (m * SK + ks + a_kof) * 2);
            }
            uint32_t bf[2][4];
#pragma unroll
            for (int nfp = 0; nfp < 2; nfp++) {
                int n = warp_n * 32 + nfp * 16 + b_row;
                ldsm4(bf[nfp], bbb + (n * SK + ks + b_kof) * 2);
            }
#pragma unroll
            for (int mf = 0; mf < 4; mf++)
#pragma unroll
                for (int nf = 0; nf < 4; nf++)
                    mma_f16(acc[mf][nf], af[mf], &bf[nf >> 1][(nf & 1) * 2]);
        }
        __syncthreads();
    }

#pragma unroll
    for (int mf = 0; mf < 4; mf++) {
        int m0 = bm + warp_m * 64 + mf * 16 + grp;
#pragma unroll
        for (int nf = 0; nf < 4; nf++) {
            int n0 = bn + warp_n * 32 + nf * 8 + 2 * tig;
            float b0 = bias[n0], b1 = bias[n0 + 1];
            if (m0 < NN) {
                float v0 = softplusf(acc[mf][nf][0] + b0);
                float v1 = softplusf(acc[mf][nf][1] + b1);
                *(__half2*)(out + (size_t)m0 * Fout + n0) = __floats2half2_rn(v0, v1);
            }
            if (m0 + 8 < NN) {
                float v0 = softplusf(acc[mf][nf][2] + b0);
                float v1 = softplusf(acc[mf][nf][3] + b1);
                *(__half2*)(out + (size_t)(m0 + 8) * Fout + n0) = __floats2half2_rn(v0, v1);
            }
        }
    }
}

// ---------------------------------------------------------------------------
// Narrow fp16 tc GEMM (Fout = 16/32/64): BM=128 (16 rows/warp), BK=16,
// B fully smem-resident, A streamed through 3-stage cp.async ring.
template<int BN, int FIN>
__global__ __launch_bounds__(256) void gemm3_tc_n(
        const __half* __restrict__ A0, const __half* __restrict__ A1,
        const __half* __restrict__ A2, const __half* __restrict__ Wt,
        const float* __restrict__ bias, __half* __restrict__ out) {
    constexpr int KT = 3 * FIN;
    constexpr int BK = 16;
    constexpr int T = KT / BK;
    constexpr int SKA = 24;            // halves; CF ldmatrix
    constexpr int SKB = KT + 8;        // halves; CF for KT in {48,96,384}
    constexpr int ASZ = 128 * SKA;
    constexpr int NF = BN / 8;
    __shared__ __align__(16) __half sA[3][ASZ];
    __shared__ __align__(16) __half sB[BN * SKB];

    const int tid = threadIdx.x;
    const int lane = tid & 31;
    const int warp = tid >> 5;         // rows [warp*16, warp*16+16)
    const int bm = blockIdx.x * 128;
    const int grp = lane >> 2;
    const int tig = lane & 3;

    const uint32_t sA_base = smem_u32(&sA[0][0]);
    const uint32_t sB_base = smem_u32(&sB[0]);

    const int a_row = (lane & 7) + ((lane >> 3) & 1) * 8;
    const int a_kof = ((lane >> 4) & 1) * 8;
    const int b_row = (lane & 7) + ((lane >> 4) & 1) * 8;
    const int b_kof = ((lane >> 3) & 1) * 8;

    float acc[NF][4];
#pragma unroll
    for (int i = 0; i < NF; i++)
#pragma unroll
        for (int v = 0; v < 4; v++) acc[i][v] = 0.f;

    const __half* As[3] = {A0, A1, A2};

    // B: whole (KT x BN) resident, loaded once (group with A tile 0)
    constexpr int KC = KT / 8;
    for (int idx = tid; idx < BN * KC; idx += 256) {
        int n = idx / KC, c = idx - n * KC;
        int kt = c * 8;
        int s = kt / FIN, k = kt - s * FIN;
        cp_async16(sB_base + (n * SKB + kt) * 2,
                   Wt + (size_t)s * FIN * BN + (size_t)n * FIN + k, 16);
    }

    auto load_tileA = [&](int t, int st) {
        int k0 = t * BK;
        int s = k0 / FIN, koff = k0 - s * FIN;
        const __half* Ap = As[s];
        int r = tid >> 1, kc = (tid & 1) * 8;
        int gm = bm + r;
        cp_async16(sA_base + (st * ASZ + r * SKA + kc) * 2,
                   Ap + (size_t)gm * FIN + koff + kc, gm < NN ? 16 : 0);
    };

    load_tileA(0, 0);
    cp_commit();                       // group: B + A0
    if (T > 1) { load_tileA(1, 1); cp_commit(); }

    for (int t = 0; t < T; t++) {
        int st = t % 3;
        if (t + 2 < T) {
            load_tileA(t + 2, (t + 2) % 3);
            cp_commit();
            asm volatile("cp.async.wait_group 2;\n" ::: "memory");
        } else if (t + 1 < T) {
            asm volatile("cp.async.wait_group 1;\n" ::: "memory");
        } else {
            asm volatile("cp.async.wait_group 0;\n" ::: "memory");
        }
        __syncthreads();

        uint32_t af[4];
        ldsm4(af, sA_base + (st * ASZ + (warp * 16 + a_row) * SKA + a_kof) * 2);
        uint32_t bf[(NF + 1) / 2][4];
#pragma unroll
        for (int nfp = 0; nfp < (NF + 1) / 2; nfp++)
            ldsm4(bf[nfp], sB_base + ((nfp * 16 + b_row) * SKB + t * BK + b_kof) * 2);
#pragma unroll
        for (int nf = 0; nf < NF; nf++)
            mma_f16(acc[nf], af, &bf[nf >> 1][(nf & 1) * 2]);
        __syncthreads();
    }

    int m0 = bm + warp * 16 + grp;
#pragma unroll
    for (int nf = 0; nf < NF; nf++) {
        int n0 = nf * 8 + 2 * tig;
        float b0 = bias[n0], b1 = bias[n0 + 1];
        if (m0 < NN) {
            float v0 = softplusf(acc[nf][0] + b0);
            float v1 = softplusf(acc[nf][1] + b1);
            *(__half2*)(out + (size_t)m0 * BN + n0) = __floats2half2_rn(v0, v1);
        }
        if (m0 + 8 < NN) {
            float v0 = softplusf(acc[nf][2] + b0);
            float v1 = softplusf(acc[nf][3] + b1);
            *(__half2*)(out + (size_t)(m0 + 8) * BN + n0) = __floats2half2_rn(v0, v1);
        }
    }
}

// final FC: out[n][0:3] = h[n][0:512] @ fc_w (512x3) + fc_b; one warp per node, fp16 h
__global__ void fc_kernel(const __half* __restrict__ h, const float* __restrict__ fw,
                          const float* __restrict__ fb, float* __restrict__ out) {
    int gw = (blockIdx.x * blockDim.x + threadIdx.x) >> 5;
    int lane = threadIdx.x & 31;
    if (gw >= NN) return;
    const __half* hr = h + (size_t)gw * 512;
    float a0 = 0.f, a1 = 0.f, a2 = 0.f;
    for (int i = lane; i < 512; i += 32) {
        float v = __half2float(hr[i]);
        a0 = fmaf(v, fw[i * 3 + 0], a0);
        a1 = fmaf(v, fw[i * 3 + 1], a1);
        a2 = fmaf(v, fw[i * 3 + 2], a2);
    }
#pragma unroll
    for (int o = 16; o > 0; o >>= 1) {
        a0 += __shfl_down_sync(0xffffffffu, a0, o);
        a1 += __shfl_down_sync(0xffffffffu, a1, o);
        a2 += __shfl_down_sync(0xffffffffu, a2, o);
    }
    if (lane == 0) {
        out[gw * 3 + 0] = a0 + fb[0];
        out[gw * 3 + 1] = a1 + fb[1];
        out[gw * 3 + 2] = a2 + fb[2];
    }
}

// ---------------------------------------------------------------------------

extern "C" void kernel_launch(void* const* d_in, const int* in_sizes, int n_in,
                              void* d_out, int out_size) {
    (void)in_sizes; (void)n_in; (void)out_size;

    const float* x   = (const float*)d_in[0];
    const int*   ei  = (const int*)d_in[1];
    const float* ew  = (const float*)d_in[2];
    const float* Wp[6];
    const float* bp[6];
    for (int l = 0; l < 6; l++) {
        Wp[l] = (const float*)d_in[4 + 2 * l];
        bp[l] = (const float*)d_in[5 + 2 * l];
    }
    const float* fcw = (const float*)d_in[16];
    const float* fcb = (const float*)d_in[17];
    float* out = (float*)d_out;

    uint4 *x16, *hA, *hB, *t1h, *t2h, *wh;
    float *deg;
    int *cnt;
    cudaGetSymbolAddress((void**)&x16, g_x16);
    cudaGetSymbolAddress((void**)&hA,  g_hA);
    cudaGetSymbolAddress((void**)&hB,  g_hB);
    cudaGetSymbolAddress((void**)&t1h, g_t1h);
    cudaGetSymbolAddress((void**)&t2h, g_t2h);
    cudaGetSymbolAddress((void**)&wh,  g_wh);
    cudaGetSymbolAddress((void**)&deg, g_deg);
    cudaGetSymbolAddress((void**)&cnt, g_cnt);

    const int* row = ei;
    const int* col = ei + EE;

    // wide kernel needs 60KB dynamic smem
    cudaFuncSetAttribute(gemm3_tc_h, cudaFuncAttributeMaxDynamicSharedMemorySize, 61440);

    // one-shot conversions (x -> fp16, all weights -> fp16 transposed) in one launch
    conv_all<<<(XV4 + WTOT + 255) / 256, 256>>>(
        (const float4*)x, (__half2*)x16,
        Wp[0], Wp[1], Wp[2], Wp[3], Wp[4], Wp[5], (__half*)wh);

    // CSC build
    cudaMemsetAsync(deg, 0, NN * sizeof(float));
    cudaMemsetAsync(cnt, 0, NN * sizeof(int));
    deg_count_kernel<<<(EE + 255) / 256, 256>>>(row, col, ew);
    scan1_kernel<<<NCHUNK, SCB>>>();
    scan2_kernel<<<1, 32>>>();
    scan3_kernel<<<NCHUNK, SCB>>>();
    fill_kernel<<<(EE + 255) / 256, 256>>>(row, col, ew);

    const __half* wh_h = (const __half*)wh;
    const int woff[6] = {0, 6144, 7680, 13824, 38400, 136704};
    const int FINs[7] = {128, 16, 32, 64, 128, 256, 512};

    uint4* hin = x16;
    uint4* hout = hA;
    for (int l = 0; l < 6; l++) {
        int Fin = FINs[l], Fout = FINs[l + 1];
        int FV = Fin / 8;
        int npb = 256 / FV;
        unsigned gb = (NN + npb - 1) / npb;

        spmm_gather_h<<<gb, 256>>>(hin, nullptr, 1.f, 0.f, t1h, FV, npb);
        spmm_gather_h<<<gb, 256>>>(t1h, hin, 2.f, -1.f, t2h, FV, npb);

        const __half* A0 = (const __half*)hin;
        const __half* A1 = (const __half*)t1h;
        const __half* A2 = (const __half*)t2h;
        __half* O = (__half*)hout;
        unsigned gx = (NN + 127) / 128;
        if (Fout == 16)
            gemm3_tc_n<16, 128><<<gx, 256>>>(A0, A1, A2, wh_h + woff[l], bp[l], O);
        else if (Fout == 32)
            gemm3_tc_n<32, 16><<<gx, 256>>>(A0, A1, A2, wh_h + woff[l], bp[l], O);
        else if (Fout == 64)
            gemm3_tc_n<64, 32><<<gx, 256>>>(A0, A1, A2, wh_h + woff[l], bp[l], O);
        else {
            dim3 grid(gx, Fout / 128);
            gemm3_tc_h<<<grid, 256, 61440>>>(A0, A1, A2, wh_h + woff[l], bp[l], O,
                                             Fin, Fout);
        }

        // ping-pong (x16 only ever an input)
        hin = hout;
        hout = (hin == hA) ? hB : hA;
    }

    // final FC 512 -> 3
    fc_kernel<<<((long)NN * 32 + 255) / 256, 256>>>((const __half*)hin, fcw, fcb, out);
}

// round 17
// speedup vs baseline: 6.0695x; 1.1439x over previous
#include <cuda_runtime.h>
#include <cuda_fp16.h>
#include <math.h>
#include <stdint.h>

#define NN 30000
#define EE 480000
#define SCB 1024
#define NCHUNK ((NN + SCB - 1) / SCB)   // 30

// dims per layer: input 128 -> 16 -> 32 -> 64 -> 128 -> 256 -> 512

// Scratch (static __device__ arrays; no allocations allowed)
__device__ uint4  g_x16[(size_t)NN * 16];        // x in fp16 (NN x 128)
__device__ uint4  g_hA[(size_t)NN * 64];         // fp16 ping-pong (up to NN x 512)
__device__ uint4  g_hB[(size_t)NN * 64];
__device__ uint4  g_t1h[(size_t)NN * 32];        // fp16 Tx (up to NN x 256); layer0: P (N x 48)
__device__ uint4  g_t2h[(size_t)NN * 32];        // layer0: Q (N x 32)
__device__ uint4  g_wh[66240];                   // fp16 transposed weights, all 6 layers
__device__ float  g_deg[NN];
__device__ int    g_cnt[NN];
__device__ int    g_ptr[NN + 1];
__device__ int    g_cur[NN];
__device__ float2 g_edge[EE];                    // packed (srcidx-bits, weight) per CSC slot
__device__ int    g_bsum[32];

// ---------------------------------------------------------------------------
__device__ __forceinline__ float softplusf(float x) {
    return fmaxf(x, 0.f) + log1pf(__expf(-fabsf(x)));
}

__device__ __forceinline__ uint32_t smem_u32(const void* p) {
    return (uint32_t)__cvta_generic_to_shared(p);
}

__device__ __forceinline__ void cp_async16(uint32_t dst, const void* src, int srcBytes) {
    asm volatile("cp.async.ca.shared.global [%0], [%1], 16, %2;\n"
                 :: "r"(dst), "l"(src), "r"(srcBytes));
}
__device__ __forceinline__ void cp_commit() {
    asm volatile("cp.async.commit_group;\n" ::: "memory");
}

__device__ __forceinline__ void ldsm4(uint32_t (&r)[4], uint32_t addr) {
    asm volatile("ldmatrix.sync.aligned.m8n8.x4.shared.b16 {%0,%1,%2,%3}, [%4];"
                 : "=r"(r[0]), "=r"(r[1]), "=r"(r[2]), "=r"(r[3]) : "r"(addr));
}

__device__ __forceinline__ void mma_f16(float (&d)[4], const uint32_t (&a)[4],
                                        const uint32_t* b) {
    asm volatile(
        "mma.sync.aligned.m16n8k16.row.col.f32.f16.f16.f32 "
        "{%0,%1,%2,%3},{%4,%5,%6,%7},{%8,%9},{%0,%1,%2,%3};"
        : "+f"(d[0]), "+f"(d[1]), "+f"(d[2]), "+f"(d[3])
        : "r"(a[0]), "r"(a[1]), "r"(a[2]), "r"(a[3]), "r"(b[0]), "r"(b[1]));
}

// ---------------------------------------------------------------------------
// One-shot: x fp32->fp16, all 6 W tensors -> (3,Fout,Fin) fp16 transposed,
// zero deg/cnt, init out = fc_b.
#define XV4 (NN * 32)
#define WTOT 529920
__global__ void conv_all(const float4* __restrict__ x, __half2* __restrict__ x16,
                         const float* W0, const float* W1, const float* W2,
                         const float* W3, const float* W4, const float* W5,
                         __half* __restrict__ dst,
                         const float* __restrict__ fcb, float* __restrict__ out) {
    int idx = blockIdx.x * blockDim.x + threadIdx.x;
    if (idx < XV4) {
        float4 v = x[idx];
        x16[2 * idx + 0] = __floats2half2_rn(v.x, v.y);
        x16[2 * idx + 1] = __floats2half2_rn(v.z, v.w);
        return;
    }
    idx -= XV4;
    if (idx < WTOT) {
        const int offs[7]  = {0, 6144, 7680, 13824, 38400, 136704, WTOT};
        const int fins[6]  = {128, 16, 32, 64, 128, 256};
        const int fouts[6] = {16, 32, 64, 128, 256, 512};
        const float* Ws[6] = {W0, W1, W2, W3, W4, W5};
        int l = 0;
        while (idx >= offs[l + 1]) l++;
        int rem = idx - offs[l];
        int Fin = fins[l], Fout = fouts[l];
        int s = rem / (Fin * Fout);
        int r2 = rem - s * Fin * Fout;
        int k = r2 / Fout, n = r2 - k * Fout;
        dst[(size_t)offs[l] + (size_t)s * Fin * Fout + (size_t)n * Fin + k] =
            __float2half_rn(Ws[l][rem]);
        return;
    }
    idx -= WTOT;
    if (idx < NN) {
        g_deg[idx] = 0.f;
        g_cnt[idx] = 0;
        float b0 = fcb[0], b1 = fcb[1], b2 = fcb[2];
        out[idx * 3 + 0] = b0;
        out[idx * 3 + 1] = b1;
        out[idx * 3 + 2] = b2;
    }
}

// ---------------------------------------------------------------------------
// CSC build
__global__ void deg_count_kernel(const int* __restrict__ row, const int* __restrict__ col,
                                 const float* __restrict__ ew) {
    int e = blockIdx.x * blockDim.x + threadIdx.x;
    if (e < EE) {
        atomicAdd(&g_deg[row[e]], ew[e]);
        atomicAdd(&g_cnt[col[e]], 1);
    }
}

// scan pass 1: chunk-local exclusive scan + chunk sums
__global__ void scan1_kernel() {
    const int b = blockIdx.x, tid = threadIdx.x;
    const int lane = tid & 31, wid = tid >> 5;
    __shared__ int wsum[32];
    int i = b * SCB + tid;
    int v = (i < NN) ? g_cnt[i] : 0;
    int incl = v;
#pragma unroll
    for (int o = 1; o < 32; o <<= 1) {
        int t = __shfl_up_sync(0xffffffffu, incl, o);
        if (lane >= o) incl += t;
    }
    if (lane == 31) wsum[wid] = incl;
    __syncthreads();
    if (wid == 0) {
        int s = wsum[lane];
        int inc2 = s;
#pragma unroll
        for (int o = 1; o < 32; o <<= 1) {
            int t = __shfl_up_sync(0xffffffffu, inc2, o);
            if (lane >= o) inc2 += t;
        }
        wsum[lane] = inc2 - s;
    }
    __syncthreads();
    int excl = wsum[wid] + incl - v;
    if (i < NN) g_ptr[i] = excl;
    if (tid == SCB - 1) g_bsum[b] = excl + v;
}

// scan pass 2: each block re-reduces chunk sums (tiny) and adds its offset
__global__ void scan3_kernel() {
    __shared__ int s_off;
    int b = blockIdx.x;
    if (threadIdx.x < 32) {
        int v = ((int)threadIdx.x < b) ? g_bsum[threadIdx.x] : 0;
#pragma unroll
        for (int o = 16; o > 0; o >>= 1) v += __shfl_down_sync(0xffffffffu, v, o);
        if (threadIdx.x == 0) s_off = v;
    }
    __syncthreads();
    int i = b * SCB + threadIdx.x;
    if (i < NN) {
        int p = g_ptr[i] + s_off;
        g_ptr[i] = p;
        g_cur[i] = p;
    }
    if (b == NCHUNK - 1 && threadIdx.x == SCB - 1)
        g_ptr[NN] = s_off + g_bsum[NCHUNK - 1];
}

__global__ void fill_kernel(const int* __restrict__ row, const int* __restrict__ col,
                            const float* __restrict__ ew) {
    int e = blockIdx.x * blockDim.x + threadIdx.x;
    if (e < EE) {
        int c = col[e];
        int p = atomicAdd(&g_cur[c], 1);
        int r = row[e];
        float d = g_deg[r];
        float w = (d > 0.f) ? (-ew[e] / d) : 0.f;
        g_edge[p] = make_float2(__int_as_float(r), w);
    }
}

// ---------------------------------------------------------------------------
// fp16 gather SpMM with stride/offset (uint4 units). fp32 accumulate.
// dst[c*dStr+dOff+tx] = half( scale*sum w[e]*src[srcidx[e]*sStr+sOff+tx] + addscale*addsrc )
__global__ void spmm_gather_h(const uint4* __restrict__ src, const uint4* __restrict__ addsrc,
                              float scale, float addscale, uint4* __restrict__ dst,
                              int FV, int npb, int sStr, int sOff, int dStr, int dOff) {
    int ty = threadIdx.x / FV;
    int tx = threadIdx.x - ty * FV;
    int c = blockIdx.x * npb + ty;
    if (c >= NN) return;
    int beg = g_ptr[c], end = g_ptr[c + 1];
    float2 acc[4];
#pragma unroll
    for (int q = 0; q < 4; q++) acc[q] = make_float2(0.f, 0.f);

    if (FV >= 8) {
        int wlane = threadIdx.x & 31;
        int gbase = wlane & ~(FV - 1);
        unsigned gmask = (FV == 32) ? 0xffffffffu : (((1u << FV) - 1u) << gbase);
        for (int eb = beg; eb < end; eb += FV) {
            int n = end - eb; if (n > FV) n = FV;
            int r_l = 0; float w_l = 0.f;
            if (tx < n) {
                float2 e = g_edge[eb + tx];
                r_l = __float_as_int(e.x);
                w_l = e.y;
            }
            for (int j = 0; j < n; j++) {
                int r = __shfl_sync(gmask, r_l, gbase + j);
                float w = __shfl_sync(gmask, w_l, gbase + j);
                uint4 v = src[(size_t)r * sStr + sOff + tx];
                const __half2* hp = (const __half2*)&v;
#pragma unroll
                for (int q = 0; q < 4; q++) {
                    float2 f = __half22float2(hp[q]);
                    acc[q].x = fmaf(w, f.x, acc[q].x);
                    acc[q].y = fmaf(w, f.y, acc[q].y);
                }
            }
        }
    } else {
        for (int e = beg; e < end; e++) {
            float2 ed = g_edge[e];
            int r = __float_as_int(ed.x);
            float w = ed.y;
            uint4 v = src[(size_t)r * sStr + sOff + tx];
            const __half2* hp = (const __half2*)&v;
#pragma unroll
            for (int q = 0; q < 4; q++) {
                float2 f = __half22float2(hp[q]);
                acc[q].x = fmaf(w, f.x, acc[q].x);
                acc[q].y = fmaf(w, f.y, acc[q].y);
            }
        }
    }

    uint4 r;
    __half2* rp = (__half2*)&r;
    if (addsrc) {
        uint4 a = addsrc[(size_t)c * sStr + sOff + tx];
        const __half2* ap = (const __half2*)&a;
#pragma unroll
        for (int q = 0; q < 4; q++) {
            float2 af = __half22float2(ap[q]);
            rp[q] = __floats2half2_rn(fmaf(addscale, af.x, scale * acc[q].x),
                                      fmaf(addscale, af.y, scale * acc[q].y));
        }
    } else {
#pragma unroll
        for (int q = 0; q < 4; q++)
            rp[q] = __floats2half2_rn(scale * acc[q].x, scale * acc[q].y);
    }
    dst[(size_t)c * dStr + dOff + tx] = r;
}

// Layer-0 final: h1[c] = softplus(P0[c] - P2[c] + Q1[c] + 2*(L*Q2)[c] + b).
// P = N x 48 halves (6 u4: P0 cols 0-15, P1 16-31, P2 32-47); Q = N x 32 (4 u4: Q1,Q2).
__global__ void spmm_l0_final(const uint4* __restrict__ P, const uint4* __restrict__ Q,
                              const float* __restrict__ bias, uint4* __restrict__ dst) {
    int c = blockIdx.x * 128 + (threadIdx.x >> 1);
    int tx = threadIdx.x & 1;
    if (c >= NN) return;
    int beg = g_ptr[c], end = g_ptr[c + 1];
    float2 acc[4];
#pragma unroll
    for (int q = 0; q < 4; q++) acc[q] = make_float2(0.f, 0.f);
    for (int e = beg; e < end; e++) {
        float2 ed = g_edge[e];
        int r = __float_as_int(ed.x);
        float w = ed.y;
        uint4 v = Q[(size_t)r * 4 + 2 + tx];          // Q2 half of r's row
        const __half2* hp = (const __half2*)&v;
#pragma unroll
        for (int q = 0; q < 4; q++) {
            float2 f = __half22float2(hp[q]);
            acc[q].x = fmaf(w, f.x, acc[q].x);
            acc[q].y = fmaf(w, f.y, acc[q].y);
        }
    }
    uint4 p0 = P[(size_t)c * 6 + tx];
    uint4 p2 = P[(size_t)c * 6 + 4 + tx];
    uint4 q1 = Q[(size_t)c * 4 + tx];
    const __half2* p0h = (const __half2*)&p0;
    const __half2* p2h = (const __half2*)&p2;
    const __half2* q1h = (const __half2*)&q1;
    uint4 r;
    __half2* rp = (__half2*)&r;
#pragma unroll
    for (int q = 0; q < 4; q++) {
        float2 f0 = __half22float2(p0h[q]);
        float2 f2 = __half22float2(p2h[q]);
        float2 fq = __half22float2(q1h[q]);
        float bx = bias[tx * 8 + 2 * q], by = bias[tx * 8 + 2 * q + 1];
        float ox = softplusf(f0.x - f2.x + fq.x + 2.f * acc[q].x + bx);
        float oy = softplusf(f0.y - f2.y + fq.y + 2.f * acc[q].y + by);
        rp[q] = __floats2half2_rn(ox, oy);
    }
    dst[(size_t)c * 2 + tx] = r;
}

// ---------------------------------------------------------------------------
// Layer-0 projection GEMM: P[N x 48] = x16[N x 128] @ W48^T, no bias/activation.
// W48 is rows n48 in [0,48), stride 128 halves (the existing (3,16,128) transpose).
__global__ __launch_bounds__(256) void gemm_p48(
        const __half* __restrict__ A, const __half* __restrict__ Wt,
        __half* __restrict__ out) {
    constexpr int BK = 16, T = 8;      // KT = 128
    constexpr int SKA = 24, SKB = 136;
    constexpr int ASZ = 128 * SKA;
    constexpr int NF = 6;              // 48 / 8
    __shared__ __align__(16) __half sA[3][ASZ];
    __shared__ __align__(16) __half sB[48 * SKB];

    const int tid = threadIdx.x;
    const int lane = tid & 31;
    const int warp = tid >> 5;
    const int bm = blockIdx.x * 128;
    const int grp = lane >> 2;
    const int tig = lane & 3;

    const uint32_t sA_base = smem_u32(&sA[0][0]);
    const uint32_t sB_base = smem_u32(&sB[0]);

    const int a_row = (lane & 7) + ((lane >> 3) & 1) * 8;
    const int a_kof = ((lane >> 4) & 1) * 8;
    const int b_row = (lane & 7) + ((lane >> 4) & 1) * 8;
    const int b_kof = ((lane >> 3) & 1) * 8;

    float acc[NF][4];
#pragma unroll
    for (int i = 0; i < NF; i++)
#pragma unroll
        for (int v = 0; v < 4; v++) acc[i][v] = 0.f;

    // B resident: 48 rows x 128 halves = 768 chunks
    for (int idx = tid; idx < 48 * 16; idx += 256) {
        int n = idx >> 4, k = (idx & 15) * 8;
        cp_async16(sB_base + (n * SKB + k) * 2, Wt + (size_t)n * 128 + k, 16);
    }

    auto load_tileA = [&](int t, int st) {
        int r = tid >> 1, kc = (tid & 1) * 8;
        int gm = bm + r;
        cp_async16(sA_base + (st * ASZ + r * SKA + kc) * 2,
                   A + (size_t)gm * 128 + t * BK + kc, gm < NN ? 16 : 0);
    };

    load_tileA(0, 0);
    cp_commit();
    load_tileA(1, 1);
    cp_commit();

    for (int t = 0; t < T; t++) {
        int st = t % 3;
        if (t + 2 < T) {
            load_tileA(t + 2, (t + 2) % 3);
            cp_commit();
            asm volatile("cp.async.wait_group 2;\n" ::: "memory");
        } else if (t + 1 < T) {
            asm volatile("cp.async.wait_group 1;\n" ::: "memory");
        } else {
            asm volatile("cp.async.wait_group 0;\n" ::: "memory");
        }
        __syncthreads();

        uint32_t af[4];
        ldsm4(af, sA_base + (st * ASZ + (warp * 16 + a_row) * SKA + a_kof) * 2);
        uint32_t bf[3][4];
#pragma unroll
        for (int nfp = 0; nfp < 3; nfp++)
            ldsm4(bf[nfp], sB_base + ((nfp * 16 + b_row) * SKB + t * BK + b_kof) * 2);
#pragma unroll
        for (int nf = 0; nf < NF; nf++)
            mma_f16(acc[nf], af, &bf[nf >> 1][(nf & 1) * 2]);
        __syncthreads();
    }

    int m0 = bm + warp * 16 + grp;
#pragma unroll
    for (int nf = 0; nf < NF; nf++) {
        int n0 = nf * 8 + 2 * tig;
        if (m0 < NN)
            *(__half2*)(out + (size_t)m0 * 48 + n0) = __floats2half2_rn(acc[nf][0], acc[nf][1]);
        if (m0 + 8 < NN)
            *(__half2*)(out + (size_t)(m0 + 8) * 48 + n0) = __floats2half2_rn(acc[nf][2], acc[nf][3]);
    }
}

// ---------------------------------------------------------------------------
// Wide fp16 tc GEMM (Fout % 128 == 0): 128x128x32 tiles, 3-stage cp.async.
// If fcw != null: instead of storing, fold softplus(out) through the 512->3 FC
// and atomicAdd into fcout (fcout pre-initialized with fc_b).
__global__ __launch_bounds__(256) void gemm3_tc_h(
        const __half* __restrict__ A0, const __half* __restrict__ A1,
        const __half* __restrict__ A2, const __half* __restrict__ Wt,
        const float* __restrict__ bias, __half* __restrict__ out,
        int Fin, int Fout, const float* __restrict__ fcw, float* __restrict__ fcout) {
    constexpr int BK = 32;
    constexpr int SK = 40;
    constexpr int ASZ = 128 * SK;      // halves per operand per stage
    constexpr int STG = ASZ * 2;       // halves per stage (A+B)
    extern __shared__ __half smem_dyn[];

    const int tid = threadIdx.x;
    const int lane = tid & 31;
    const int warp = tid >> 5;
    const int warp_m = warp & 1;
    const int warp_n = warp >> 1;
    const int bm = blockIdx.x * 128, bn = blockIdx.y * 128;
    const int grp = lane >> 2;
    const int tig = lane & 3;

    const uint32_t s_base = smem_u32(smem_dyn);
    float* sfw = (float*)(smem_dyn + 3 * STG);   // 6144 B when fcw != null

    if (fcw) {
        for (int i = tid; i < 1536; i += 256) sfw[i] = fcw[i];
    }

    const int a_row = (lane & 7) + ((lane >> 3) & 1) * 8;
    const int a_kof = ((lane >> 4) & 1) * 8;
    const int b_row = (lane & 7) + ((lane >> 4) & 1) * 8;
    const int b_kof = ((lane >> 3) & 1) * 8;

    float acc[4][4][4];
#pragma unroll
    for (int i = 0; i < 4; i++)
#pragma unroll
        for (int j = 0; j < 4; j++)
#pragma unroll
            for (int v = 0; v < 4; v++) acc[i][j][v] = 0.f;

    const __half* As[3] = {A0, A1, A2};
    const int KT = 3 * Fin;
    const int T = KT / BK;

    auto load_tile = [&](int t, int st) {
        int k0 = t * BK;
        int seg = k0 / Fin;
        int koff = k0 - seg * Fin;
        const __half* Ap = As[seg];
        const __half* Bp = Wt + (size_t)seg * Fin * Fout;
        uint32_t da = s_base + (st * STG) * 2;
        uint32_t db = da + ASZ * 2;
#pragma unroll
        for (int i = 0; i < 2; i++) {
            int chunk = tid + i * 256;
            int r = chunk >> 2;
            int kc = (chunk & 3) * 8;
            int gm = bm + r;
            cp_async16(da + (r * SK + kc) * 2, Ap + (size_t)gm * Fin + koff + kc,
                       gm < NN ? 16 : 0);
            int gn = bn + r;
            cp_async16(db + (r * SK + kc) * 2, Bp + (size_t)gn * Fin + koff + kc, 16);
        }
        cp_commit();
    };

    load_tile(0, 0);
    load_tile(1, 1);

    for (int t = 0; t < T; t++) {
        int st = t % 3;
        if (t + 2 < T) {
            load_tile(t + 2, (t + 2) % 3);
            asm volatile("cp.async.wait_group 2;\n" ::: "memory");
        } else if (t + 1 < T) {
            asm volatile("cp.async.wait_group 1;\n" ::: "memory");
        } else {
            asm volatile("cp.async.wait_group 0;\n" ::: "memory");
        }
        __syncthreads();

        uint32_t aab = s_base + (st * STG) * 2;
        uint32_t bbb = aab + ASZ * 2;
#pragma unroll
        for (int ks = 0; ks < BK; ks += 16) {
            uint32_t af[4][4];
#pragma unroll
            for (int mf = 0; mf < 4; mf++) {
                int m = warp_m * 64 + mf * 16 + a_row;
                ldsm4(af[mf], aab + (m * SK + ks + a_kof) * 2);
            }
            uint32_t bf[2][4];
#pragma unroll
            for (int nfp = 0; nfp < 2; nfp++) {
                int n = warp_n * 32 + nfp * 16 + b_row;
                ldsm4(bf[nfp], bbb + (n * SK + ks + b_kof) * 2);
            }
#pragma unroll
            for (int mf = 0; mf < 4; mf++)
#pragma unroll
                for (int nf = 0; nf < 4; nf++)
                    mma_f16(acc[mf][nf], af[mf], &bf[nf >> 1][(nf & 1) * 2]);
        }
        __syncthreads();
    }

    if (fcw) {
        // fused FC epilogue: per row, fold this warp's 32-col slice through fcw
#pragma unroll
        for (int mf = 0; mf < 4; mf++) {
            int m0 = bm + warp_m * 64 + mf * 16 + grp;
            float q0[3] = {0.f, 0.f, 0.f};
            float q1[3] = {0.f, 0.f, 0.f};
#pragma unroll
            for (int nf = 0; nf < 4; nf++) {
                int n0 = bn + warp_n * 32 + nf * 8 + 2 * tig;
                float b0 = bias[n0], b1 = bias[n0 + 1];
                float v0 = softplusf(acc[mf][nf][0] + b0);
                float v1 = softplusf(acc[mf][nf][1] + b1);
                float w0 = softplusf(acc[mf][nf][2] + b0);
                float w1 = softplusf(acc[mf][nf][3] + b1);
#pragma unroll
                for (int j = 0; j < 3; j++) {
                    float f0 = sfw[n0 * 3 + j], f1 = sfw[(n0 + 1) * 3 + j];
                    q0[j] = fmaf(v0, f0, fmaf(v1, f1, q0[j]));
                    q1[j] = fmaf(w0, f0, fmaf(w1, f1, q1[j]));
                }
            }
            // reduce across the 4 tig lanes of this quad (same grp)
#pragma unroll
            for (int j = 0; j < 3; j++) {
#pragma unroll
                for (int o = 1; o < 4; o <<= 1) {
                    q0[j] += __shfl_xor_sync(0xffffffffu, q0[j], o);
                    q1[j] += __shfl_xor_sync(0xffffffffu, q1[j], o);
                }
            }
            if (tig == 0) {
                if (m0 < NN)
#pragma unroll
                    for (int j = 0; j < 3; j++) atomicAdd(&fcout[m0 * 3 + j], q0[j]);
                if (m0 + 8 < NN)
#pragma unroll
                    for (int j = 0; j < 3; j++) atomicAdd(&fcout[(m0 + 8) * 3 + j], q1[j]);
            }
        }
    } else {
#pragma unroll
        for (int mf = 0; mf < 4; mf++) {
            int m0 = bm + warp_m * 64 + mf * 16 + grp;
#pragma unroll
            for (int nf = 0; nf < 4; nf++) {
                int n0 = bn + warp_n * 32 + nf * 8 + 2 * tig;
                float b0 = bias[n0], b1 = bias[n0 + 1];
                if (m0 < NN) {
                    float v0 = softplusf(acc[mf][nf][0] + b0);
                    float v1 = softplusf(acc[mf][nf][1] + b1);
                    *(__half2*)(out + (size_t)m0 * Fout + n0) = __floats2half2_rn(v0, v1);
                }
                if (m0 + 8 < NN) {
                    float v0 = softplusf(acc[mf][nf][2] + b0);
                    float v1 = softplusf(acc[mf][nf][3] + b1);
                    *(__half2*)(out + (size_t)(m0 + 8) * Fout + n0) = __floats2half2_rn(v0, v1);
                }
            }
        }
    }
}

// ---------------------------------------------------------------------------
// Narrow fp16 tc GEMM (Fout = 32/64): BM=128 (16 rows/warp), BK=16,
// B fully smem-resident, A streamed through 3-stage cp.async ring.
template<int BN, int FIN>
__global__ __launch_bounds__(256) void gemm3_tc_n(
        const __half* __restrict__ A0, const __half* __restrict__ A1,
        const __half* __restrict__ A2, const __half* __restrict__ Wt,
        const float* __restrict__ bias, __half* __restrict__ out) {
    constexpr int KT = 3 * FIN;
    constexpr int BK = 16;
    constexpr int T = KT / BK;
    constexpr int SKA = 24;
    constexpr int SKB = KT + 8;
    constexpr int ASZ = 128 * SKA;
    constexpr int NF = BN / 8;
    __shared__ __align__(16) __half sA[3][ASZ];
    __shared__ __align__(16) __half sB[BN * SKB];

    const int tid = threadIdx.x;
    const int lane = tid & 31;
    const int warp = tid >> 5;
    const int bm = blockIdx.x * 128;
    const int grp = lane >> 2;
    const int tig = lane & 3;

    const uint32_t sA_base = smem_u32(&sA[0][0]);
    const uint32_t sB_base = smem_u32(&sB[0]);

    const int a_row = (lane & 7) + ((lane >> 3) & 1) * 8;
    const int a_kof = ((lane >> 4) & 1) * 8;
    const int b_row = (lane & 7) + ((lane >> 4) & 1) * 8;
    const int b_kof = ((lane >> 3) & 1) * 8;

    float acc[NF][4];
#pragma unroll
    for (int i = 0; i < NF; i++)
#pragma unroll
        for (int v = 0; v < 4; v++) acc[i][v] = 0.f;

    const __half* As[3] = {A0, A1, A2};

    constexpr int KC = KT / 8;
    for (int idx = tid; idx < BN * KC; idx += 256) {
        int n = idx / KC, c = idx - n * KC;
        int kt = c * 8;
        int s = kt / FIN, k = kt - s * FIN;
        cp_async16(sB_base + (n * SKB + kt) * 2,
                   Wt + (size_t)s * FIN * BN + (size_t)n * FIN + k, 16);
    }

    auto load_tileA = [&](int t, int st) {
        int k0 = t * BK;
        int s = k0 / FIN, koff = k0 - s * FIN;
        const __half* Ap = As[s];
        int r = tid >> 1, kc = (tid & 1) * 8;
        int gm = bm + r;
        cp_async16(sA_base + (st * ASZ + r * SKA + kc) * 2,
                   Ap + (size_t)gm * FIN + koff + kc, gm < NN ? 16 : 0);
    };

    load_tileA(0, 0);
    cp_commit();
    if (T > 1) { load_tileA(1, 1); cp_commit(); }

    for (int t = 0; t < T; t++) {
        int st = t % 3;
        if (t + 2 < T) {
            load_tileA(t + 2, (t + 2) % 3);
            cp_commit();
            asm volatile("cp.async.wait_group 2;\n" ::: "memory");
        } else if (t + 1 < T) {
            asm volatile("cp.async.wait_group 1;\n" ::: "memory");
        } else {
            asm volatile("cp.async.wait_group 0;\n" ::: "memory");
        }
        __syncthreads();

        uint32_t af[4];
        ldsm4(af, sA_base + (st * ASZ + (warp * 16 + a_row) * SKA + a_kof) * 2);
        uint32_t bf[(NF + 1) / 2][4];
#pragma unroll
        for (int nfp = 0; nfp < (NF + 1) / 2; nfp++)
            ldsm4(bf[nfp], sB_base + ((nfp * 16 + b_row) * SKB + t * BK + b_kof) * 2);
#pragma unroll
        for (int nf = 0; nf < NF; nf++)
            mma_f16(acc[nf], af, &bf[nf >> 1][(nf & 1) * 2]);
        __syncthreads();
    }

    int m0 = bm + warp * 16 + grp;
#pragma unroll
    for (int nf = 0; nf < NF; nf++) {
        int n0 = nf * 8 + 2 * tig;
        float b0 = bias[n0], b1 = bias[n0 + 1];
        if (m0 < NN) {
            float v0 = softplusf(acc[nf][0] + b0);
            float v1 = softplusf(acc[nf][1] + b1);
            *(__half2*)(out + (size_t)m0 * BN + n0) = __floats2half2_rn(v0, v1);
        }
        if (m0 + 8 < NN) {
            float v0 = softplusf(acc[nf][2] + b0);
            float v1 = softplusf(acc[nf][3] + b1);
            *(__half2*)(out + (size_t)(m0 + 8) * BN + n0) = __floats2half2_rn(v0, v1);
        }
    }
}

// ---------------------------------------------------------------------------

extern "C" void kernel_launch(void* const* d_in, const int* in_sizes, int n_in,
                              void* d_out, int out_size) {
    (void)in_sizes; (void)n_in; (void)out_size;

    const float* x   = (const float*)d_in[0];
    const int*   ei  = (const int*)d_in[1];
    const float* ew  = (const float*)d_in[2];
    const float* Wp[6];
    const float* bp[6];
    for (int l = 0; l < 6; l++) {
        Wp[l] = (const float*)d_in[4 + 2 * l];
        bp[l] = (const float*)d_in[5 + 2 * l];
    }
    const float* fcw = (const float*)d_in[16];
    const float* fcb = (const float*)d_in[17];
    float* out = (float*)d_out;

    uint4 *x16, *hA, *hB, *t1h, *t2h, *wh;
    cudaGetSymbolAddress((void**)&x16, g_x16);
    cudaGetSymbolAddress((void**)&hA,  g_hA);
    cudaGetSymbolAddress((void**)&hB,  g_hB);
    cudaGetSymbolAddress((void**)&t1h, g_t1h);
    cudaGetSymbolAddress((void**)&t2h, g_t2h);
    cudaGetSymbolAddress((void**)&wh,  g_wh);

    const int* row = ei;
    const int* col = ei + EE;

    cudaFuncSetAttribute(gemm3_tc_h, cudaFuncAttributeMaxDynamicSharedMemorySize, 67584);

    // conversions + zero deg/cnt + init out = fc_b, one launch
    conv_all<<<(XV4 + WTOT + NN + 255) / 256, 256>>>(
        (const float4*)x, (__half2*)x16,
        Wp[0], Wp[1], Wp[2], Wp[3], Wp[4], Wp[5], (__half*)wh, fcb, out);

    // CSC build
    deg_count_kernel<<<(EE + 255) / 256, 256>>>(row, col, ew);
    scan1_kernel<<<NCHUNK, SCB>>>();
    scan3_kernel<<<NCHUNK, SCB>>>();
    fill_kernel<<<(EE + 255) / 256, 256>>>(row, col, ew);

    const __half* wh_h = (const __half*)wh;
    const int woff[6] = {0, 6144, 7680, 13824, 38400, 136704};
    const int FINs[7] = {128, 16, 32, 64, 128, 256, 512};

    // ---- layer 0 (commuted): P = x@[W0|W1|W2]; Q = L[P1|P2]; h1 = sp(P0-P2+Q1+2LQ2+b)
    gemm_p48<<<(NN + 127) / 128, 256>>>((const __half*)x16, wh_h, (__half*)t1h);
    spmm_gather_h<<<(NN + 63) / 64, 256>>>(t1h, nullptr, 1.f, 0.f, t2h,
                                           4, 64, 6, 2, 4, 0);     // Q1,Q2 = L*[P1|P2]
    spmm_l0_final<<<(NN + 127) / 128, 256>>>(t1h, t2h, bp[0], hA);

    // ---- layers 1-5
    uint4* hin = hA;
    uint4* hout = hB;
    for (int l = 1; l < 6; l++) {
        int Fin = FINs[l], Fout = FINs[l + 1];
        int FV = Fin / 8;
        int npb = 256 / FV;
        unsigned gb = (NN + npb - 1) / npb;

        spmm_gather_h<<<gb, 256>>>(hin, nullptr, 1.f, 0.f, t1h, FV, npb, FV, 0, FV, 0);
        spmm_gather_h<<<gb, 256>>>(t1h, hin, 2.f, -1.f, t2h, FV, npb, FV, 0, FV, 0);

        const __half* A0 = (const __half*)hin;
        const __half* A1 = (const __half*)t1h;
        const __half* A2 = (const __half*)t2h;
        __half* O = (__half*)hout;
        unsigned gx = (NN + 127) / 128;
        if (Fout == 32)
            gemm3_tc_n<32, 16><<<gx, 256>>>(A0, A1, A2, wh_h + woff[l], bp[l], O);
        else if (Fout == 64)
            gemm3_tc_n<64, 32><<<gx, 256>>>(A0, A1, A2, wh_h + woff[l], bp[l], O);
        else if (Fout == 512) {
            dim3 grid(gx, 4);
            gemm3_tc_h<<<grid, 256, 67584>>>(A0, A1, A2, wh_h + woff[l], bp[l], nullptr,
                                             Fin, Fout, fcw, out);   // fused FC
        } else {
            dim3 grid(gx, Fout / 128);
            gemm3_tc_h<<<grid, 256, 61440>>>(A0, A1, A2, wh_h + woff[l], bp[l], O,
                                             Fin, Fout, nullptr, nullptr);
        }

        hin = hout;
        hout = (hin == hA) ? hB : hA;
    }
}